// round 1
// baseline (speedup 1.0000x reference)
#include <cuda_runtime.h>
#include <math.h>

#define B_   4
#define S_   2048
#define D_   1024
#define H_   16
#define KD_  64
#define FF_  4096
#define BS_  (B_*S_)   // 8192

// ---------------- scratch (static device globals; no allocations) -------------
__device__ float g_Q  [H_*BS_*KD_];                 // 8.4M
__device__ float g_K  [H_*BS_*KD_];                 // 8.4M
__device__ float g_ATT[(size_t)H_*B_*S_*S_];        // 268M (1GB)
__device__ float g_TMP[BS_*D_];                     // per-head ctx
__device__ float g_AV [BS_*D_];                     // attention_values / ffn2 out
__device__ float g_X  [BS_*D_];                     // ln1 output
__device__ float g_FF [BS_*FF_];                    // ffn hidden
__device__ unsigned char g_pad[BS_];                // normalized padding mask

// ---------------- padding-mask dtype detection + normalization ----------------
// Safe: reads only the first BS_ bytes for detection (valid for bool/int32/float32),
// then reads the full buffer only once dtype is known.
__global__ void prep_mask_kernel(const void* raw)
{
    const unsigned char* bytes = (const unsigned char*)raw;
    __shared__ int sFloat, sOff, sAny;
    if (threadIdx.x == 0) { sFloat = 0; sOff = 0; sAny = 0; }
    __syncthreads();
    int lf = 0, lo = 0, la = 0;
    for (int i = threadIdx.x; i < BS_; i += blockDim.x) {
        unsigned char c = bytes[i];
        if (c) la = 1;
        if (c > 1) lf = 1;            // e.g. 0x80 / 0x3F from float 1.0f
        if ((i & 3) && c) lo = 1;     // nonzero at non-word-aligned byte
    }
    if (lf) atomicOr(&sFloat, 1);
    if (lo) atomicOr(&sOff, 1);
    if (la) atomicOr(&sAny, 1);
    __syncthreads();
    int mode;                          // 0=bool bytes, 1=int32, 2=float32
    if (!sAny)       mode = 3;         // all zero under any interpretation
    else if (sFloat) mode = 2;
    else if (sOff)   mode = 0;
    else             mode = 1;
    for (int i = threadIdx.x; i < BS_; i += blockDim.x) {
        unsigned char p;
        if (mode == 3)      p = 0;
        else if (mode == 2) p = (((const float*)raw)[i] != 0.0f);
        else if (mode == 1) p = (((const int*)raw)[i]   != 0);
        else                p = (bytes[i] != 0);
        g_pad[i] = p;
    }
}

// ---------------- generic tiled SGEMM (NN), batched via blockIdx.z -------------
// C[z] = op( alpha * (A[z] @ B[z] + bias[z]) ) [+ resid] , optional accumulate
template<int BM, int BN, int BK, int TM, int TN, bool ACCUM>
__global__ void __launch_bounds__((BM/TM)*(BN/TN))
gemm_nn(int M, int N, int K,
        const float* __restrict__ A, int lda, long long sA,
        const float* __restrict__ Bm, int ldb, long long sB,
        float* __restrict__ C, int ldc, long long sC,
        const float* __restrict__ bias, int sBias,
        const float* __restrict__ resid,
        float alpha, int relu)
{
    constexpr int NT = (BM/TM)*(BN/TN);
    __shared__ float As[BK][BM + 4];   // padded: transposed scalar stores
    __shared__ float Bs[BK][BN];       // unpadded: aligned float4 stores

    const int tid = threadIdx.x;
    const int z = blockIdx.z;
    A  += (long long)z * sA;
    Bm += (long long)z * sB;
    C  += (long long)z * sC;
    const float* biasz = bias ? (bias + (long long)z * sBias) : nullptr;

    const int m0 = blockIdx.x * BM;
    const int n0 = blockIdx.y * BN;

    float acc[TM][TN];
#pragma unroll
    for (int i = 0; i < TM; i++)
#pragma unroll
        for (int j = 0; j < TN; j++) acc[i][j] = 0.0f;

    const int ty = tid / (BN/TN);
    const int tx = tid % (BN/TN);

    for (int k0 = 0; k0 < K; k0 += BK) {
        // A tile: BM x BK, store transposed As[k][m]
        constexpr int A4 = BM * BK / 4;
        for (int i = tid; i < A4; i += NT) {
            int r  = i / (BK/4);
            int c4 = i % (BK/4);
            float4 v = *(const float4*)&A[(long long)(m0 + r) * lda + k0 + c4*4];
            As[c4*4+0][r] = v.x; As[c4*4+1][r] = v.y;
            As[c4*4+2][r] = v.z; As[c4*4+3][r] = v.w;
        }
        // B tile: BK x BN, direct
        constexpr int B4 = BK * BN / 4;
        for (int i = tid; i < B4; i += NT) {
            int r  = i / (BN/4);
            int c4 = i % (BN/4);
            *(float4*)&Bs[r][c4*4] =
                *(const float4*)&Bm[(long long)(k0 + r) * ldb + n0 + c4*4];
        }
        __syncthreads();
#pragma unroll
        for (int k = 0; k < BK; k++) {
            float ar[TM], br[TN];
#pragma unroll
            for (int i = 0; i < TM; i++) ar[i] = As[k][ty*TM + i];
#pragma unroll
            for (int j = 0; j < TN; j++) br[j] = Bs[k][tx*TN + j];
#pragma unroll
            for (int i = 0; i < TM; i++)
#pragma unroll
                for (int j = 0; j < TN; j++)
                    acc[i][j] += ar[i] * br[j];
        }
        __syncthreads();
    }

#pragma unroll
    for (int i = 0; i < TM; i++) {
        int row = m0 + ty*TM + i;
#pragma unroll
        for (int j = 0; j < TN; j++) {
            int col = n0 + tx*TN + j;
            float v = acc[i][j];
            if (biasz) v += biasz[col];
            v *= alpha;
            if (relu) v = fmaxf(v, 0.0f);
            if (resid) v += resid[(long long)row * ldc + col];
            long long idx = (long long)row * ldc + col;
            if (ACCUM) C[idx] += v; else C[idx] = v;
        }
    }
}

// ---------------- scores: Q @ K^T / sqrt(KD) with causal+padding mask ----------
__global__ void __launch_bounds__(256)
scores_kernel(const float* __restrict__ Q, const float* __restrict__ Kc,
              float* __restrict__ ATT)
{
    const int z = blockIdx.z;          // h*B + b
    const int b = z % B_;
    const int h = z / B_;
    const float* Qh = Q  + (long long)(h*BS_ + b*S_) * KD_;
    const float* Kh = Kc + (long long)(h*BS_ + b*S_) * KD_;
    float* att = ATT + (long long)z * S_ * S_;
    const unsigned char* padb = g_pad + b * S_;

    __shared__ float Qs[16][128 + 4];
    __shared__ float Ks[16][128 + 4];
    const int tid = threadIdx.x;
    const int s0 = blockIdx.x * 128;
    const int t0 = blockIdx.y * 128;

    float acc[8][8];
#pragma unroll
    for (int i = 0; i < 8; i++)
#pragma unroll
        for (int j = 0; j < 8; j++) acc[i][j] = 0.0f;

    const int ty = tid / 16, tx = tid % 16;

    for (int k0 = 0; k0 < KD_; k0 += 16) {
        for (int i = tid; i < 512; i += 256) {
            int r = i / 4, c4 = i % 4;
            float4 v = *(const float4*)&Qh[(s0 + r)*KD_ + k0 + c4*4];
            Qs[c4*4+0][r] = v.x; Qs[c4*4+1][r] = v.y;
            Qs[c4*4+2][r] = v.z; Qs[c4*4+3][r] = v.w;
            float4 w = *(const float4*)&Kh[(t0 + r)*KD_ + k0 + c4*4];
            Ks[c4*4+0][r] = w.x; Ks[c4*4+1][r] = w.y;
            Ks[c4*4+2][r] = w.z; Ks[c4*4+3][r] = w.w;
        }
        __syncthreads();
#pragma unroll
        for (int k = 0; k < 16; k++) {
            float ar[8], br[8];
#pragma unroll
            for (int i = 0; i < 8; i++) ar[i] = Qs[k][ty*8 + i];
#pragma unroll
            for (int j = 0; j < 8; j++) br[j] = Ks[k][tx*8 + j];
#pragma unroll
            for (int i = 0; i < 8; i++)
#pragma unroll
                for (int j = 0; j < 8; j++) acc[i][j] += ar[i]*br[j];
        }
        __syncthreads();
    }

    unsigned char padt[8];
#pragma unroll
    for (int j = 0; j < 8; j++) padt[j] = padb[t0 + tx*8 + j];
#pragma unroll
    for (int i = 0; i < 8; i++) {
        int s = s0 + ty*8 + i;
        unsigned char pads = padb[s];
        long long base = (long long)s * S_;
#pragma unroll
        for (int j = 0; j < 8; j++) {
            int t = t0 + tx*8 + j;
            bool masked = (t > s) || pads || padt[j];
            att[base + t] = masked ? -1e30f : acc[i][j] * 0.125f;  // 1/sqrt(64)
        }
    }
}

// ---------------- row softmax over S=2048, with all-masked -> uniform ----------
__global__ void __launch_bounds__(256)
softmax_kernel(float* __restrict__ ATT)
{
    float* p = ATT + (long long)blockIdx.x * S_;
    const int tid = threadIdx.x;
    float v[8];
    float m = -1e30f;
#pragma unroll
    for (int i = 0; i < 8; i++) { v[i] = p[tid + i*256]; m = fmaxf(m, v[i]); }
    __shared__ float red[256];
    red[tid] = m; __syncthreads();
    for (int s = 128; s > 0; s >>= 1) {
        if (tid < s) red[tid] = fmaxf(red[tid], red[tid + s]);
        __syncthreads();
    }
    float rowmax = red[0];
    __syncthreads();
    if (rowmax < -1e29f) {             // fully masked row -> reference sets to uniform
        const float u = 1.0f / (float)S_;
#pragma unroll
        for (int i = 0; i < 8; i++) p[tid + i*256] = u;
        return;
    }
    float sum = 0.0f;
#pragma unroll
    for (int i = 0; i < 8; i++) { v[i] = __expf(v[i] - rowmax); sum += v[i]; }
    red[tid] = sum; __syncthreads();
    for (int s = 128; s > 0; s >>= 1) {
        if (tid < s) red[tid] += red[tid + s];
        __syncthreads();
    }
    float inv = 1.0f / red[0];
#pragma unroll
    for (int i = 0; i < 8; i++) p[tid + i*256] = v[i] * inv;
}

// ---------------- layernorm (optional residual add) ---------------------------
__global__ void __launch_bounds__(256)
ln_kernel(float* __restrict__ out, const float* __restrict__ a,
          const float* __restrict__ r, const float* __restrict__ w,
          const float* __restrict__ bb)
{
    long long base = (long long)blockIdx.x * D_;
    const int tid = threadIdx.x;
    float x[4];
    float sum = 0.0f, sq = 0.0f;
#pragma unroll
    for (int i = 0; i < 4; i++) {
        int c = tid + i*256;
        float v = a[base + c];
        if (r) v += r[base + c];
        x[i] = v; sum += v; sq += v*v;
    }
    __shared__ float r1[256], r2[256];
    r1[tid] = sum; r2[tid] = sq; __syncthreads();
    for (int s = 128; s > 0; s >>= 1) {
        if (tid < s) { r1[tid] += r1[tid + s]; r2[tid] += r2[tid + s]; }
        __syncthreads();
    }
    float mu  = r1[0] * (1.0f / D_);
    float var = r2[0] * (1.0f / D_) - mu*mu;
    float rstd = rsqrtf(var + 1e-5f);
#pragma unroll
    for (int i = 0; i < 4; i++) {
        int c = tid + i*256;
        out[base + c] = (x[i] - mu) * rstd * w[c] + bb[c];
    }
}

// ---------------- launch --------------------------------------------------------
extern "C" void kernel_launch(void* const* d_in, const int* in_sizes, int n_in,
                              void* d_out, int out_size)
{
    const float* input = (const float*)d_in[0];
    const void*  mraw  = d_in[1];
    const float* Wq    = (const float*)d_in[2];
    const float* bq    = (const float*)d_in[3];
    const float* Wk    = (const float*)d_in[4];
    const float* bk    = (const float*)d_in[5];
    const float* Wv    = (const float*)d_in[6];
    const float* bv    = (const float*)d_in[7];
    const float* ln1w  = (const float*)d_in[8];
    const float* ln1b  = (const float*)d_in[9];
    const float* ln2w  = (const float*)d_in[10];
    const float* ln2b  = (const float*)d_in[11];
    const float* ff1w  = (const float*)d_in[12];
    const float* ff1b  = (const float*)d_in[13];
    const float* ff2w  = (const float*)d_in[14];
    const float* ff2b  = (const float*)d_in[15];
    float* out = (float*)d_out;

    float *pQ, *pK, *pATT, *pTMP, *pAV, *pX, *pFF;
    cudaGetSymbolAddress((void**)&pQ,   g_Q);
    cudaGetSymbolAddress((void**)&pK,   g_K);
    cudaGetSymbolAddress((void**)&pATT, g_ATT);
    cudaGetSymbolAddress((void**)&pTMP, g_TMP);
    cudaGetSymbolAddress((void**)&pAV,  g_AV);
    cudaGetSymbolAddress((void**)&pX,   g_X);
    cudaGetSymbolAddress((void**)&pFF,  g_FF);

    prep_mask_kernel<<<1, 256>>>(mraw);

    // Q, K projections: per-head [8192,1024] @ [1024,64] + bias, batched over H
    gemm_nn<128,64,16,8,4,false><<<dim3(BS_/128, 1, H_), 256>>>(
        BS_, KD_, D_,
        input, D_, 0LL,
        Wq, KD_, (long long)D_*KD_,
        pQ, KD_, (long long)BS_*KD_,
        bq, KD_, nullptr, 1.0f, 0);
    gemm_nn<128,64,16,8,4,false><<<dim3(BS_/128, 1, H_), 256>>>(
        BS_, KD_, D_,
        input, D_, 0LL,
        Wk, KD_, (long long)D_*KD_,
        pK, KD_, (long long)BS_*KD_,
        bk, KD_, nullptr, 1.0f, 0);

    // scores + mask, then row softmax
    scores_kernel<<<dim3(S_/128, S_/128, H_*B_), 256>>>(pQ, pK, pATT);
    softmax_kernel<<<H_*B_*S_, 256>>>(pATT);

    // V path reordered: ctx_h = attn_h @ input ; AV += (ctx_h @ Wv_h + bv_h)/H
    for (int h = 0; h < H_; h++) {
        gemm_nn<128,128,16,8,8,false><<<dim3(S_/128, D_/128, B_), 256>>>(
            S_, D_, S_,
            pATT + (size_t)h*B_*S_*S_, S_, (long long)S_*S_,
            input, D_, (long long)S_*D_,
            pTMP, D_, (long long)S_*D_,
            nullptr, 0, nullptr, 1.0f, 0);
        if (h == 0) {
            gemm_nn<128,128,16,8,8,false><<<dim3(BS_/128, D_/128, 1), 256>>>(
                BS_, D_, D_,
                pTMP, D_, 0LL,
                Wv + (size_t)h*D_*D_, D_, 0LL,
                pAV, D_, 0LL,
                bv + h*D_, 0, nullptr, 1.0f/H_, 0);
        } else {
            gemm_nn<128,128,16,8,8,true><<<dim3(BS_/128, D_/128, 1), 256>>>(
                BS_, D_, D_,
                pTMP, D_, 0LL,
                Wv + (size_t)h*D_*D_, D_, 0LL,
                pAV, D_, 0LL,
                bv + h*D_, 0, nullptr, 1.0f/H_, 0);
        }
    }

    // x = LN1(input + AV)
    ln_kernel<<<BS_, 256>>>(pX, input, pAV, ln1w, ln1b);

    // FFN
    gemm_nn<128,128,16,8,8,false><<<dim3(BS_/128, FF_/128, 1), 256>>>(
        BS_, FF_, D_,
        pX, D_, 0LL,
        ff1w, FF_, 0LL,
        pFF, FF_, 0LL,
        ff1b, 0, nullptr, 1.0f, 1 /*relu*/);
    gemm_nn<128,128,16,8,8,false><<<dim3(BS_/128, D_/128, 1), 256>>>(
        BS_, D_, FF_,
        pFF, FF_, 0LL,
        ff2w, D_, 0LL,
        pAV, D_, 0LL,
        ff2b, 0, pX /*residual*/, 1.0f, 0);

    // out = LN2(x + ff)
    ln_kernel<<<BS_, 256>>>(out, pAV, nullptr, ln2w, ln2b);
}

// round 5
// speedup vs baseline: 4.7426x; 4.7426x over previous
#include <cuda_runtime.h>
#include <math.h>
#include <stdint.h>

#define B_   4
#define S_   2048
#define D_   1024
#define H_   16
#define KD_  64
#define FF_  4096
#define BS_  (B_*S_)   // 8192
#define HD_  (H_*D_)   // 16384

// ---------------- scratch (static device globals; no allocations) -------------
__device__ float g_Q  [BS_*D_];                     // Q proj [s][(h,kd)]
__device__ float g_K  [BS_*D_];                     // K proj
__device__ float g_ATT[(size_t)H_*B_*S_*S_];        // attention probs, 1GB
__device__ float g_CTX[(size_t)BS_*HD_];            // per-head contexts, 512MB
__device__ float g_AV [BS_*D_];                     // attention_values / ffn2 out
__device__ float g_X  [BS_*D_];                     // ln1 output
__device__ float g_FF [BS_*FF_];                    // ffn hidden
__device__ float g_Wq2[D_*D_];                      // repacked Wq  [d][(h,kd)]
__device__ float g_Wk2[D_*D_];                      // repacked Wk
__device__ float g_bvm[D_];                         // mean_h bv / H
__device__ float g_cm [B_*D_];                      // column sums of input per batch
__device__ unsigned char g_pad[BS_];                // normalized padding mask

// ---------------- padding-mask dtype detection + normalization ----------------
__global__ void prep_mask_kernel(const void* raw)
{
    const unsigned char* bytes = (const unsigned char*)raw;
    __shared__ int sFloat, sOff, sAny;
    if (threadIdx.x == 0) { sFloat = 0; sOff = 0; sAny = 0; }
    __syncthreads();
    int lf = 0, lo = 0, la = 0;
    for (int i = threadIdx.x; i < BS_; i += blockDim.x) {
        unsigned char c = bytes[i];
        if (c) la = 1;
        if (c > 1) lf = 1;
        if ((i & 3) && c) lo = 1;
    }
    if (lf) atomicOr(&sFloat, 1);
    if (lo) atomicOr(&sOff, 1);
    if (la) atomicOr(&sAny, 1);
    __syncthreads();
    int mode;                          // 0=bool bytes, 1=int32, 2=float32, 3=all zero
    if (!sAny)       mode = 3;
    else if (sFloat) mode = 2;
    else if (sOff)   mode = 0;
    else             mode = 1;
    for (int i = threadIdx.x; i < BS_; i += blockDim.x) {
        unsigned char p;
        if (mode == 3)      p = 0;
        else if (mode == 2) p = (((const float*)raw)[i] != 0.0f);
        else if (mode == 1) p = (((const int*)raw)[i]   != 0);
        else                p = (bytes[i] != 0);
        g_pad[i] = p;
    }
}

// ---------------- weight repack: Wq[h][d][k] -> Wq2[d][h*64+k] -----------------
__global__ void repack_wqk_kernel(const float* __restrict__ Wq,
                                  const float* __restrict__ Wk)
{
    int i = blockIdx.x * 256 + threadIdx.x;      // over H*D*KD = 2^20
    int k = i & 63;
    int d = (i >> 6) & 1023;
    int h = i >> 16;
    g_Wq2[d*D_ + h*KD_ + k] = Wq[i];
    g_Wk2[d*D_ + h*KD_ + k] = Wk[i];
}

__global__ void bv_mean_kernel(const float* __restrict__ bv)
{
    int e = blockIdx.x * 256 + threadIdx.x;
    float s = 0.0f;
#pragma unroll
    for (int h = 0; h < H_; h++) s += bv[h*D_ + e];
    g_bvm[e] = s * (1.0f / H_);
}

// ---------------- column sums of input (for padded-row fixup) ------------------
__global__ void zero_cm_kernel()
{
    g_cm[blockIdx.x * 256 + threadIdx.x] = 0.0f;
}
__global__ void colsum_kernel(const float* __restrict__ input)
{
    int b  = blockIdx.x >> 5;
    int tc = blockIdx.x & 31;
    int e4 = threadIdx.x * 4;
    const float* base = input + (long long)b*S_*D_ + (long long)tc*64*D_;
    float4 s = make_float4(0.f, 0.f, 0.f, 0.f);
    for (int t = 0; t < 64; t++) {
        float4 v = *(const float4*)&base[(long long)t*D_ + e4];
        s.x += v.x; s.y += v.y; s.z += v.z; s.w += v.w;
    }
    atomicAdd(&g_cm[b*D_ + e4 + 0], s.x);
    atomicAdd(&g_cm[b*D_ + e4 + 1], s.y);
    atomicAdd(&g_cm[b*D_ + e4 + 2], s.z);
    atomicAdd(&g_cm[b*D_ + e4 + 3], s.w);
}
// padded rows: CTX[row][(h,e)] = colmean(input_b)[e] for all heads
__global__ void ctx_fixup_kernel()
{
    int row = blockIdx.x;
    if (!g_pad[row]) return;
    int b = row / S_;
    int e = threadIdx.x * 4;
    float4 v = *(const float4*)&g_cm[b*D_ + e];
    const float inv = 1.0f / (float)S_;
    v.x *= inv; v.y *= inv; v.z *= inv; v.w *= inv;
    float* dst = g_CTX + (size_t)row * HD_;
#pragma unroll
    for (int h = 0; h < H_; h++)
        *(float4*)&dst[h*D_ + e] = v;
}

// ---------------- tf32 tensor-core GEMM (static smem, BK=16, 2-stage) ----------
__device__ __forceinline__ uint32_t f2tf(float f)
{
    uint32_t r;
    asm("cvt.rna.tf32.f32 %0, %1;" : "=r"(r) : "f"(f));
    return r;
}
__device__ __forceinline__ void cp16(void* smem, const void* g)
{
    uint32_t s = (uint32_t)__cvta_generic_to_shared(smem);
    asm volatile("cp.async.cg.shared.global [%0], [%1], 16;\n" :: "r"(s), "l"(g));
}
#define CP_COMMIT() asm volatile("cp.async.commit_group;\n" ::)
#define CP_WAIT1()  asm volatile("cp.async.wait_group 1;\n" ::)

__device__ __forceinline__ void mma_tf32(float* d, const uint32_t* a, const uint32_t* b)
{
    asm volatile(
        "mma.sync.aligned.m16n8k8.row.col.f32.tf32.tf32.f32 "
        "{%0,%1,%2,%3},{%4,%5,%6,%7},{%8,%9},{%0,%1,%2,%3};"
        : "+f"(d[0]), "+f"(d[1]), "+f"(d[2]), "+f"(d[3])
        : "r"(a[0]), "r"(a[1]), "r"(a[2]), "r"(a[3]), "r"(b[0]), "r"(b[1]));
}

#define ASTRIDE 24          // 16 + 8 pad (floats)
#define BSTRIDE 136         // 128 + 8 pad
#define ATILE (128*ASTRIDE) // 3072 floats
#define BTILE (16*BSTRIDE)  // 2176 floats
#define STAGEF (ATILE + BTILE) // 5248 floats = 21KB; 2 stages = 42KB static

// C = alpha*(A@B) [+bias] [relu] [+resid]; tri!=0 => K truncated to m0+128
template<bool RELU, bool RESID>
__global__ void __launch_bounds__(256)
mma_gemm(int M, int N, int K,
         const float* __restrict__ A, int lda, long long sAh, long long sAb,
         const float* __restrict__ Bm, int ldb, long long sBh, long long sBb,
         float* __restrict__ C, int ldc, long long sCh, long long sCb,
         const float* __restrict__ bias, const float* __restrict__ resid,
         float alpha, int zB, int tri)
{
    __shared__ float sm[2*STAGEF];
    const int tid = threadIdx.x;
    const int z = blockIdx.z;
    const int zh = z / zB, zb = z % zB;
    A    += zh*sAh + zb*sAb;
    Bm   += zh*sBh + zb*sBb;
    long long coff = zh*sCh + zb*sCb;
    C    += coff;
    const float* res = RESID ? (resid + coff) : nullptr;

    const int m0 = blockIdx.x * 128;
    const int n0 = blockIdx.y * 128;

    const int warp = tid >> 5, lane = tid & 31;
    const int wm = warp >> 1, wn = warp & 1;     // 4x2 warps, warp tile 32x64
    const int grp = lane >> 2, tig = lane & 3;

    float acc[2][8][4];
#pragma unroll
    for (int i = 0; i < 2; i++)
#pragma unroll
        for (int j = 0; j < 8; j++)
#pragma unroll
            for (int k = 0; k < 4; k++) acc[i][j][k] = 0.0f;

    int Ke = tri ? (m0 + 128 < K ? m0 + 128 : K) : K;
    const int nk = Ke >> 4;   // K/16

    auto load_tile = [&](int st, int k0) {
        float* As = sm + st*STAGEF;
        float* Bs = sm + st*STAGEF + ATILE;
#pragma unroll
        for (int i = 0; i < 2; i++) {            // 512 float4 for A (128x16)
            int idx = tid + i*256;
            int r  = idx >> 2, c4 = idx & 3;
            cp16(&As[r*ASTRIDE + c4*4], &A[(long long)(m0 + r)*lda + k0 + c4*4]);
        }
#pragma unroll
        for (int i = 0; i < 2; i++) {            // 512 float4 for B (16x128)
            int idx = tid + i*256;
            int r  = idx >> 5, c4 = idx & 31;
            cp16(&Bs[r*BSTRIDE + c4*4], &Bm[(long long)(k0 + r)*ldb + n0 + c4*4]);
        }
    };

    load_tile(0, 0);
    CP_COMMIT();

    for (int kt = 0; kt < nk; kt++) {
        if (kt + 1 < nk) load_tile((kt + 1) & 1, (kt + 1) << 4);
        CP_COMMIT();
        CP_WAIT1();
        __syncthreads();

        const float* As = sm + (kt & 1)*STAGEF;
        const float* Bs = sm + (kt & 1)*STAGEF + ATILE;
#pragma unroll
        for (int kk = 0; kk < 16; kk += 8) {
            uint32_t af[2][4], bf[8][2];
#pragma unroll
            for (int mt = 0; mt < 2; mt++) {
                int row = wm*32 + mt*16;
                af[mt][0] = f2tf(As[(row + grp    )*ASTRIDE + kk + tig    ]);
                af[mt][1] = f2tf(As[(row + grp + 8)*ASTRIDE + kk + tig    ]);
                af[mt][2] = f2tf(As[(row + grp    )*ASTRIDE + kk + tig + 4]);
                af[mt][3] = f2tf(As[(row + grp + 8)*ASTRIDE + kk + tig + 4]);
            }
#pragma unroll
            for (int nt = 0; nt < 8; nt++) {
                int col = wn*64 + nt*8 + grp;
                bf[nt][0] = f2tf(Bs[(kk + tig    )*BSTRIDE + col]);
                bf[nt][1] = f2tf(Bs[(kk + tig + 4)*BSTRIDE + col]);
            }
#pragma unroll
            for (int mt = 0; mt < 2; mt++)
#pragma unroll
                for (int nt = 0; nt < 8; nt++)
                    mma_tf32(acc[mt][nt], af[mt], bf[nt]);
        }
        __syncthreads();
    }

#pragma unroll
    for (int mt = 0; mt < 2; mt++) {
        int r0 = m0 + wm*32 + mt*16 + grp;
#pragma unroll
        for (int nt = 0; nt < 8; nt++) {
            int c = n0 + wn*64 + nt*8 + tig*2;
            float v00 = acc[mt][nt][0]*alpha, v01 = acc[mt][nt][1]*alpha;
            float v10 = acc[mt][nt][2]*alpha, v11 = acc[mt][nt][3]*alpha;
            if (bias) {
                float2 bv2 = *(const float2*)&bias[c];
                v00 += bv2.x; v01 += bv2.y; v10 += bv2.x; v11 += bv2.y;
            }
            if (RELU) {
                v00 = fmaxf(v00, 0.0f); v01 = fmaxf(v01, 0.0f);
                v10 = fmaxf(v10, 0.0f); v11 = fmaxf(v11, 0.0f);
            }
            long long i0 = (long long)r0*ldc + c;
            long long i1 = (long long)(r0 + 8)*ldc + c;
            if (RESID) {
                float2 e0 = *(const float2*)&res[i0];
                float2 e1 = *(const float2*)&res[i1];
                v00 += e0.x; v01 += e0.y; v10 += e1.x; v11 += e1.y;
            }
            *(float2*)&C[i0] = make_float2(v00, v01);
            *(float2*)&C[i1] = make_float2(v10, v11);
        }
    }
}

// ---------------- scores: Q @ K^T / 8, lower+diagonal tiles only ---------------
__global__ void __launch_bounds__(256)
scores_kernel(const float* __restrict__ Q, const float* __restrict__ Kc,
              float* __restrict__ ATT)
{
    const int s0 = blockIdx.x * 128;
    const int t0 = blockIdx.y * 128;
    if (t0 > s0) return;               // strictly-upper tile: never read downstream

    const int z = blockIdx.z;          // h*B + b
    const int b = z % B_;
    const int h = z / B_;
    float* att = ATT + (long long)z * S_ * S_;
    const int tid = threadIdx.x;

    const float* Qh = Q  + (long long)(b*S_)*D_ + h*KD_;
    const float* Kh = Kc + (long long)(b*S_)*D_ + h*KD_;
    const unsigned char* padb = g_pad + b*S_;

    __shared__ float Qs[16][128 + 4];
    __shared__ float Ks[16][128 + 4];

    float acc[8][8];
#pragma unroll
    for (int i = 0; i < 8; i++)
#pragma unroll
        for (int j = 0; j < 8; j++) acc[i][j] = 0.0f;

    const int ty = tid / 16, tx = tid % 16;

    for (int k0 = 0; k0 < KD_; k0 += 16) {
        for (int i = tid; i < 512; i += 256) {
            int r = i / 4, c4 = i % 4;
            float4 v = *(const float4*)&Qh[(long long)(s0 + r)*D_ + k0 + c4*4];
            Qs[c4*4+0][r] = v.x; Qs[c4*4+1][r] = v.y;
            Qs[c4*4+2][r] = v.z; Qs[c4*4+3][r] = v.w;
            float4 w = *(const float4*)&Kh[(long long)(t0 + r)*D_ + k0 + c4*4];
            Ks[c4*4+0][r] = w.x; Ks[c4*4+1][r] = w.y;
            Ks[c4*4+2][r] = w.z; Ks[c4*4+3][r] = w.w;
        }
        __syncthreads();
#pragma unroll
        for (int k = 0; k < 16; k++) {
            float ar[8], br[8];
#pragma unroll
            for (int i = 0; i < 8; i++) ar[i] = Qs[k][ty*8 + i];
#pragma unroll
            for (int j = 0; j < 8; j++) br[j] = Ks[k][tx*8 + j];
#pragma unroll
            for (int i = 0; i < 8; i++)
#pragma unroll
                for (int j = 0; j < 8; j++) acc[i][j] += ar[i]*br[j];
        }
        __syncthreads();
    }

    unsigned char padt[8];
#pragma unroll
    for (int j = 0; j < 8; j++) padt[j] = padb[t0 + tx*8 + j];
#pragma unroll
    for (int i = 0; i < 8; i++) {
        int s = s0 + ty*8 + i;
        unsigned char pads = padb[s];
        long long base = (long long)s * S_;
#pragma unroll
        for (int j = 0; j < 8; j++) {
            int t = t0 + tx*8 + j;
            bool masked = (t > s) || pads || padt[j];
            att[base + t] = masked ? -1e30f : acc[i][j] * 0.125f;
        }
    }
}

// ---------------- causal softmax: read [0,s], write [0,roundup128(s+1)) --------
__global__ void __launch_bounds__(256)
softmax_kernel(float* __restrict__ ATT)
{
    const long long row = blockIdx.x;
    const int s = (int)(row % S_);
    float* p = ATT + row * S_;
    const int tid = threadIdx.x;
    const int L  = s + 1;
    const int Lw = ((s >> 7) + 1) << 7;   // round_up(s+1, 128)

    float v[8];
    float m = -1e30f;
#pragma unroll
    for (int j = 0; j < 8; j++) {
        int i = tid + j*256;
        v[j] = (i < L) ? p[i] : -1e30f;
        m = fmaxf(m, v[j]);
    }
    __shared__ float red[256];
    red[tid] = m; __syncthreads();
    for (int st = 128; st > 0; st >>= 1) {
        if (tid < st) red[tid] = fmaxf(red[tid], red[tid + st]);
        __syncthreads();
    }
    float rowmax = red[0];
    __syncthreads();
    if (rowmax < -1e29f) {                // fully masked row: zero (fixup later)
#pragma unroll
        for (int j = 0; j < 8; j++) {
            int i = tid + j*256;
            if (i < Lw) p[i] = 0.0f;
        }
        return;
    }
    float sum = 0.0f;
#pragma unroll
    for (int j = 0; j < 8; j++) {
        int i = tid + j*256;
        if (i < L) { v[j] = __expf(v[j] - rowmax); sum += v[j]; }
        else v[j] = 0.0f;
    }
    red[tid] = sum; __syncthreads();
    for (int st = 128; st > 0; st >>= 1) {
        if (tid < st) red[tid] += red[tid + st];
        __syncthreads();
    }
    float inv = 1.0f / red[0];
#pragma unroll
    for (int j = 0; j < 8; j++) {
        int i = tid + j*256;
        if (i < L) p[i] = v[j] * inv;
        else if (i < Lw) p[i] = 0.0f;
    }
}

// ---------------- layernorm (optional residual add) ---------------------------
__global__ void __launch_bounds__(256)
ln_kernel(float* __restrict__ out, const float* __restrict__ a,
          const float* __restrict__ r, const float* __restrict__ w,
          const float* __restrict__ bb)
{
    long long base = (long long)blockIdx.x * D_;
    const int tid = threadIdx.x;
    float x[4];
    float sum = 0.0f, sq = 0.0f;
#pragma unroll
    for (int i = 0; i < 4; i++) {
        int c = tid + i*256;
        float v = a[base + c];
        if (r) v += r[base + c];
        x[i] = v; sum += v; sq += v*v;
    }
    __shared__ float r1[256], r2[256];
    r1[tid] = sum; r2[tid] = sq; __syncthreads();
    for (int s = 128; s > 0; s >>= 1) {
        if (tid < s) { r1[tid] += r1[tid + s]; r2[tid] += r2[tid + s]; }
        __syncthreads();
    }
    float mu  = r1[0] * (1.0f / D_);
    float var = r2[0] * (1.0f / D_) - mu*mu;
    float rstd = rsqrtf(var + 1e-5f);
#pragma unroll
    for (int i = 0; i < 4; i++) {
        int c = tid + i*256;
        out[base + c] = (x[i] - mu) * rstd * w[c] + bb[c];
    }
}

// ---------------- launch --------------------------------------------------------
extern "C" void kernel_launch(void* const* d_in, const int* in_sizes, int n_in,
                              void* d_out, int out_size)
{
    const float* input = (const float*)d_in[0];
    const void*  mraw  = d_in[1];
    const float* Wq    = (const float*)d_in[2];
    const float* bq    = (const float*)d_in[3];
    const float* Wk    = (const float*)d_in[4];
    const float* bk    = (const float*)d_in[5];
    const float* Wv    = (const float*)d_in[6];
    const float* bv    = (const float*)d_in[7];
    const float* ln1w  = (const float*)d_in[8];
    const float* ln1b  = (const float*)d_in[9];
    const float* ln2w  = (const float*)d_in[10];
    const float* ln2b  = (const float*)d_in[11];
    const float* ff1w  = (const float*)d_in[12];
    const float* ff1b  = (const float*)d_in[13];
    const float* ff2w  = (const float*)d_in[14];
    const float* ff2b  = (const float*)d_in[15];
    float* out = (float*)d_out;

    float *pQ, *pK, *pATT, *pCTX, *pAV, *pX, *pFF, *pWq2, *pWk2, *pBvm;
    cudaGetSymbolAddress((void**)&pQ,   g_Q);
    cudaGetSymbolAddress((void**)&pK,   g_K);
    cudaGetSymbolAddress((void**)&pATT, g_ATT);
    cudaGetSymbolAddress((void**)&pCTX, g_CTX);
    cudaGetSymbolAddress((void**)&pAV,  g_AV);
    cudaGetSymbolAddress((void**)&pX,   g_X);
    cudaGetSymbolAddress((void**)&pFF,  g_FF);
    cudaGetSymbolAddress((void**)&pWq2, g_Wq2);
    cudaGetSymbolAddress((void**)&pWk2, g_Wk2);
    cudaGetSymbolAddress((void**)&pBvm, g_bvm);

    prep_mask_kernel<<<1, 256>>>(mraw);
    repack_wqk_kernel<<<4096, 256>>>(Wq, Wk);
    bv_mean_kernel<<<4, 256>>>(bv);
    zero_cm_kernel<<<B_*D_/256, 256>>>();
    colsum_kernel<<<B_*32, 256>>>(input);

    // Q, K projections: [8192,1024] @ [1024,1024]
    mma_gemm<false,false><<<dim3(BS_/128, D_/128, 1), 256>>>(
        BS_, D_, D_,
        input, D_, 0LL, 0LL,
        pWq2, D_, 0LL, 0LL,
        pQ, D_, 0LL, 0LL,
        bq, nullptr, 1.0f, 1, 0);
    mma_gemm<false,false><<<dim3(BS_/128, D_/128, 1), 256>>>(
        BS_, D_, D_,
        input, D_, 0LL, 0LL,
        pWk2, D_, 0LL, 0LL,
        pK, D_, 0LL, 0LL,
        bk, nullptr, 1.0f, 1, 0);

    // scores (lower tiles only) + causal softmax
    scores_kernel<<<dim3(S_/128, S_/128, H_*B_), 256>>>(pQ, pK, pATT);
    softmax_kernel<<<H_*B_*S_, 256>>>(pATT);

    // CTX = attn_h,b @ input_b  (triangular-truncated K), then padded-row fixup
    mma_gemm<false,false><<<dim3(S_/128, D_/128, H_*B_), 256>>>(
        S_, D_, S_,
        pATT, S_, (long long)B_*S_*S_, (long long)S_*S_,
        input, D_, 0LL, (long long)S_*D_,
        pCTX, HD_, (long long)D_, (long long)S_*HD_,
        nullptr, nullptr, 1.0f, B_, 1 /*tri*/);
    ctx_fixup_kernel<<<BS_, 256>>>();

    // AV = CTX[8192,16384] @ Wv_flat[16384,1024] / H + mean bias
    mma_gemm<false,false><<<dim3(BS_/128, D_/128, 1), 256>>>(
        BS_, D_, HD_,
        pCTX, HD_, 0LL, 0LL,
        Wv, D_, 0LL, 0LL,
        pAV, D_, 0LL, 0LL,
        pBvm, nullptr, 1.0f/H_, 1, 0);

    // x = LN1(input + AV)
    ln_kernel<<<BS_, 256>>>(pX, input, pAV, ln1w, ln1b);

    // FFN
    mma_gemm<true,false><<<dim3(BS_/128, FF_/128, 1), 256>>>(
        BS_, FF_, D_,
        pX, D_, 0LL, 0LL,
        ff1w, FF_, 0LL, 0LL,
        pFF, FF_, 0LL, 0LL,
        ff1b, nullptr, 1.0f, 1, 0);
    mma_gemm<false,true><<<dim3(BS_/128, D_/128, 1), 256>>>(
        BS_, D_, FF_,
        pFF, FF_, 0LL, 0LL,
        ff2w, D_, 0LL, 0LL,
        pAV, D_, 0LL, 0LL,
        ff2b, pX, 1.0f, 1, 0);

    // out = LN2(x + ff)
    ln_kernel<<<BS_, 256>>>(out, pAV, nullptr, ln2w, ln2b);
}

// round 6
// speedup vs baseline: 5.1131x; 1.0781x over previous
#include <cuda_runtime.h>
#include <math.h>
#include <stdint.h>

#define B_   4
#define S_   2048
#define D_   1024
#define H_   16
#define KD_  64
#define FF_  4096
#define BS_  (B_*S_)   // 8192
#define HD_  (H_*D_)   // 16384

// ---------------- scratch (static device globals; no allocations) -------------
__device__ float g_Q  [BS_*D_];                     // Q proj, tf32 bits
__device__ float g_K  [BS_*D_];                     // K proj, tf32 bits
__device__ float g_ATT[(size_t)H_*B_*S_*S_];        // scores fp32 -> probs tf32
__device__ float g_CTX[(size_t)BS_*HD_];            // per-head contexts, tf32 bits
__device__ float g_AV [BS_*D_];                     // attention_values / ffn2 out (fp32)
__device__ float g_X  [BS_*D_];                     // ln1 output fp32
__device__ float g_X32[BS_*D_];                     // ln1 output tf32 bits
__device__ float g_FF [BS_*FF_];                    // ffn hidden, tf32 bits
__device__ float g_Wq2[D_*D_];                      // repacked Wq, tf32
__device__ float g_Wk2[D_*D_];                      // repacked Wk, tf32
__device__ float g_IN32 [BS_*D_];                   // input, tf32 bits
__device__ float g_Wv32 [HD_*D_];                   // Wv flat, tf32 bits
__device__ float g_ff1w32[D_*FF_];                  // ff1w, tf32 bits
__device__ float g_ff2w32[FF_*D_];                  // ff2w, tf32 bits
__device__ float g_bvm[D_];                         // mean_h bv / H (fp32)
__device__ float g_cm [B_*D_];                      // column sums of input per batch
__device__ unsigned char g_pad[BS_];                // normalized padding mask

__device__ __forceinline__ uint32_t f2tf(float f)
{
    uint32_t r;
    asm("cvt.rna.tf32.f32 %0, %1;" : "=r"(r) : "f"(f));
    return r;
}
__device__ __forceinline__ float f2tff(float f) { return __uint_as_float(f2tf(f)); }

// ---------------- padding-mask dtype detection + normalization ----------------
__global__ void prep_mask_kernel(const void* raw)
{
    const unsigned char* bytes = (const unsigned char*)raw;
    __shared__ int sFloat, sOff, sAny;
    if (threadIdx.x == 0) { sFloat = 0; sOff = 0; sAny = 0; }
    __syncthreads();
    int lf = 0, lo = 0, la = 0;
    for (int i = threadIdx.x; i < BS_; i += blockDim.x) {
        unsigned char c = bytes[i];
        if (c) la = 1;
        if (c > 1) lf = 1;
        if ((i & 3) && c) lo = 1;
    }
    if (lf) atomicOr(&sFloat, 1);
    if (lo) atomicOr(&sOff, 1);
    if (la) atomicOr(&sAny, 1);
    __syncthreads();
    int mode;
    if (!sAny)       mode = 3;
    else if (sFloat) mode = 2;
    else if (sOff)   mode = 0;
    else             mode = 1;
    for (int i = threadIdx.x; i < BS_; i += blockDim.x) {
        unsigned char p;
        if (mode == 3)      p = 0;
        else if (mode == 2) p = (((const float*)raw)[i] != 0.0f);
        else if (mode == 1) p = (((const int*)raw)[i]   != 0);
        else                p = (bytes[i] != 0);
        g_pad[i] = p;
    }
}

// ---------------- fp32 -> tf32-bits bulk convert -------------------------------
__global__ void cvt_tf32_kernel(float* __restrict__ dst, const float* __restrict__ src,
                                int n4)
{
    int i = blockIdx.x * 256 + threadIdx.x;
    if (i >= n4) return;
    float4 v = ((const float4*)src)[i];
    v.x = f2tff(v.x); v.y = f2tff(v.y); v.z = f2tff(v.z); v.w = f2tff(v.w);
    ((float4*)dst)[i] = v;
}

// ---------------- weight repack: Wq[h][d][k] -> Wq2[d][h*64+k] (tf32) ----------
__global__ void repack_wqk_kernel(const float* __restrict__ Wq,
                                  const float* __restrict__ Wk)
{
    int i = blockIdx.x * 256 + threadIdx.x;      // over H*D*KD = 2^20
    int k = i & 63;
    int d = (i >> 6) & 1023;
    int h = i >> 16;
    g_Wq2[d*D_ + h*KD_ + k] = f2tff(Wq[i]);
    g_Wk2[d*D_ + h*KD_ + k] = f2tff(Wk[i]);
}

__global__ void bv_mean_kernel(const float* __restrict__ bv)
{
    int e = blockIdx.x * 256 + threadIdx.x;
    float s = 0.0f;
#pragma unroll
    for (int h = 0; h < H_; h++) s += bv[h*D_ + e];
    g_bvm[e] = s * (1.0f / H_);
}

// ---------------- column sums of input (for padded-row fixup) ------------------
__global__ void zero_cm_kernel()
{
    g_cm[blockIdx.x * 256 + threadIdx.x] = 0.0f;
}
__global__ void colsum_kernel(const float* __restrict__ input)
{
    int b  = blockIdx.x >> 5;
    int tc = blockIdx.x & 31;
    int e4 = threadIdx.x * 4;
    const float* base = input + (long long)b*S_*D_ + (long long)tc*64*D_;
    float4 s = make_float4(0.f, 0.f, 0.f, 0.f);
    for (int t = 0; t < 64; t++) {
        float4 v = *(const float4*)&base[(long long)t*D_ + e4];
        s.x += v.x; s.y += v.y; s.z += v.z; s.w += v.w;
    }
    atomicAdd(&g_cm[b*D_ + e4 + 0], s.x);
    atomicAdd(&g_cm[b*D_ + e4 + 1], s.y);
    atomicAdd(&g_cm[b*D_ + e4 + 2], s.z);
    atomicAdd(&g_cm[b*D_ + e4 + 3], s.w);
}
// padded rows: CTX[row][(h,e)] = colmean(input_b)[e] for all heads (tf32 bits)
__global__ void ctx_fixup_kernel()
{
    int row = blockIdx.x;
    if (!g_pad[row]) return;
    int b = row / S_;
    int e = threadIdx.x * 4;
    float4 v = *(const float4*)&g_cm[b*D_ + e];
    const float inv = 1.0f / (float)S_;
    v.x = f2tff(v.x * inv); v.y = f2tff(v.y * inv);
    v.z = f2tff(v.z * inv); v.w = f2tff(v.w * inv);
    float* dst = g_CTX + (size_t)row * HD_;
#pragma unroll
    for (int h = 0; h < H_; h++)
        *(float4*)&dst[h*D_ + e] = v;
}

// ---------------- cp.async helpers ---------------------------------------------
__device__ __forceinline__ void cp16(void* smem, const void* g)
{
    uint32_t s = (uint32_t)__cvta_generic_to_shared(smem);
    asm volatile("cp.async.cg.shared.global [%0], [%1], 16;\n" :: "r"(s), "l"(g));
}
#define CP_COMMIT() asm volatile("cp.async.commit_group;\n" ::)
#define CP_WAIT1()  asm volatile("cp.async.wait_group 1;\n" ::)

__device__ __forceinline__ void mma_tf32(float* d, const uint32_t* a, const uint32_t* b)
{
    asm volatile(
        "mma.sync.aligned.m16n8k8.row.col.f32.tf32.tf32.f32 "
        "{%0,%1,%2,%3},{%4,%5,%6,%7},{%8,%9},{%0,%1,%2,%3};"
        : "+f"(d[0]), "+f"(d[1]), "+f"(d[2]), "+f"(d[3])
        : "r"(a[0]), "r"(a[1]), "r"(a[2]), "r"(a[3]), "r"(b[0]), "r"(b[1]));
}

// ---------------- tf32 tensor-core GEMM (operands pre-converted in gmem) -------
#define ASTRIDE 24          // 16 + 8 pad (floats)
#define BSTRIDE 136         // 128 + 8 pad
#define ATILE (128*ASTRIDE)
#define BTILE (16*BSTRIDE)
#define STAGEF (ATILE + BTILE) // 21KB per stage; 2 stages = 42KB static

// C = alpha*(A@B) [+bias] [relu] [+resid]; tri => K truncated to m0+128
template<bool RELU, bool RESID, bool OUTTF>
__global__ void __launch_bounds__(256)
mma_gemm(int M, int N, int K,
         const float* __restrict__ A, int lda, long long sAh, long long sAb,
         const float* __restrict__ Bm, int ldb, long long sBh, long long sBb,
         float* __restrict__ C, int ldc, long long sCh, long long sCb,
         const float* __restrict__ bias, const float* __restrict__ resid,
         float alpha, int zB, int tri)
{
    __shared__ float sm[2*STAGEF];
    const int tid = threadIdx.x;
    const int z = blockIdx.z;
    const int zh = z / zB, zb = z % zB;
    A    += zh*sAh + zb*sAb;
    Bm   += zh*sBh + zb*sBb;
    long long coff = zh*sCh + zb*sCb;
    C    += coff;
    const float* res = RESID ? (resid + coff) : nullptr;

    const int m0 = blockIdx.x * 128;
    const int n0 = blockIdx.y * 128;

    const int warp = tid >> 5, lane = tid & 31;
    const int wm = warp >> 1, wn = warp & 1;     // 4x2 warps, warp tile 32x64
    const int grp = lane >> 2, tig = lane & 3;

    float acc[2][8][4];
#pragma unroll
    for (int i = 0; i < 2; i++)
#pragma unroll
        for (int j = 0; j < 8; j++)
#pragma unroll
            for (int k = 0; k < 4; k++) acc[i][j][k] = 0.0f;

    int Ke = tri ? (m0 + 128 < K ? m0 + 128 : K) : K;
    const int nk = Ke >> 4;   // K/16

    auto load_tile = [&](int st, int k0) {
        float* As = sm + st*STAGEF;
        float* Bs = sm + st*STAGEF + ATILE;
#pragma unroll
        for (int i = 0; i < 2; i++) {
            int idx = tid + i*256;
            int r  = idx >> 2, c4 = idx & 3;
            cp16(&As[r*ASTRIDE + c4*4], &A[(long long)(m0 + r)*lda + k0 + c4*4]);
        }
#pragma unroll
        for (int i = 0; i < 2; i++) {
            int idx = tid + i*256;
            int r  = idx >> 5, c4 = idx & 31;
            cp16(&Bs[r*BSTRIDE + c4*4], &Bm[(long long)(k0 + r)*ldb + n0 + c4*4]);
        }
    };

    load_tile(0, 0);
    CP_COMMIT();

    for (int kt = 0; kt < nk; kt++) {
        if (kt + 1 < nk) load_tile((kt + 1) & 1, (kt + 1) << 4);
        CP_COMMIT();
        CP_WAIT1();
        __syncthreads();

        const float* As = sm + (kt & 1)*STAGEF;
        const float* Bs = sm + (kt & 1)*STAGEF + ATILE;
#pragma unroll
        for (int kk = 0; kk < 16; kk += 8) {
            uint32_t af[2][4], bf[8][2];
#pragma unroll
            for (int mt = 0; mt < 2; mt++) {
                int row = wm*32 + mt*16;
                af[mt][0] = __float_as_uint(As[(row + grp    )*ASTRIDE + kk + tig    ]);
                af[mt][1] = __float_as_uint(As[(row + grp + 8)*ASTRIDE + kk + tig    ]);
                af[mt][2] = __float_as_uint(As[(row + grp    )*ASTRIDE + kk + tig + 4]);
                af[mt][3] = __float_as_uint(As[(row + grp + 8)*ASTRIDE + kk + tig + 4]);
            }
#pragma unroll
            for (int nt = 0; nt < 8; nt++) {
                int col = wn*64 + nt*8 + grp;
                bf[nt][0] = __float_as_uint(Bs[(kk + tig    )*BSTRIDE + col]);
                bf[nt][1] = __float_as_uint(Bs[(kk + tig + 4)*BSTRIDE + col]);
            }
#pragma unroll
            for (int mt = 0; mt < 2; mt++)
#pragma unroll
                for (int nt = 0; nt < 8; nt++)
                    mma_tf32(acc[mt][nt], af[mt], bf[nt]);
        }
        __syncthreads();
    }

#pragma unroll
    for (int mt = 0; mt < 2; mt++) {
        int r0 = m0 + wm*32 + mt*16 + grp;
#pragma unroll
        for (int nt = 0; nt < 8; nt++) {
            int c = n0 + wn*64 + nt*8 + tig*2;
            float v00 = acc[mt][nt][0]*alpha, v01 = acc[mt][nt][1]*alpha;
            float v10 = acc[mt][nt][2]*alpha, v11 = acc[mt][nt][3]*alpha;
            if (bias) {
                float2 bv2 = *(const float2*)&bias[c];
                v00 += bv2.x; v01 += bv2.y; v10 += bv2.x; v11 += bv2.y;
            }
            if (RELU) {
                v00 = fmaxf(v00, 0.0f); v01 = fmaxf(v01, 0.0f);
                v10 = fmaxf(v10, 0.0f); v11 = fmaxf(v11, 0.0f);
            }
            long long i0 = (long long)r0*ldc + c;
            long long i1 = (long long)(r0 + 8)*ldc + c;
            if (RESID) {
                float2 e0 = *(const float2*)&res[i0];
                float2 e1 = *(const float2*)&res[i1];
                v00 += e0.x; v01 += e0.y; v10 += e1.x; v11 += e1.y;
            }
            if (OUTTF) {
                v00 = f2tff(v00); v01 = f2tff(v01);
                v10 = f2tff(v10); v11 = f2tff(v11);
            }
            *(float2*)&C[i0] = make_float2(v00, v01);
            *(float2*)&C[i1] = make_float2(v10, v11);
        }
    }
}

// ---------------- scores on tensor cores: Q @ K^T / 8, lower tiles only --------
#define QSTR 24             // A tile stride (16+8)
#define KSTR 20             // B tile stride (16+4), conflict-free (verified)
#define SQTILE (128*QSTR)
#define SKTILE (128*KSTR)
#define SSTAGE (SQTILE + SKTILE)   // 5632 floats = 22.5KB; 2 stages = 45KB

__global__ void __launch_bounds__(256)
scores_mma_kernel(const float* __restrict__ Q, const float* __restrict__ Kc,
                  float* __restrict__ ATT)
{
    const int s0 = blockIdx.x * 128;
    const int t0 = blockIdx.y * 128;
    if (t0 > s0) return;               // strictly-upper tile: never read downstream

    __shared__ float sm[2*SSTAGE];
    const int z = blockIdx.z;          // h*B + b
    const int b = z % B_;
    const int h = z / B_;
    float* att = ATT + (long long)z * S_ * S_;
    const int tid = threadIdx.x;

    const float* Qh = Q  + (long long)(b*S_)*D_ + h*KD_;
    const float* Kh = Kc + (long long)(b*S_)*D_ + h*KD_;
    const unsigned char* padb = g_pad + b*S_;

    const int warp = tid >> 5, lane = tid & 31;
    const int wm = warp >> 1, wn = warp & 1;
    const int grp = lane >> 2, tig = lane & 3;

    float acc[2][8][4];
#pragma unroll
    for (int i = 0; i < 2; i++)
#pragma unroll
        for (int j = 0; j < 8; j++)
#pragma unroll
            for (int k = 0; k < 4; k++) acc[i][j][k] = 0.0f;

    auto load_tile = [&](int st, int k0) {
        float* Qs = sm + st*SSTAGE;
        float* Ks = sm + st*SSTAGE + SQTILE;
#pragma unroll
        for (int i = 0; i < 2; i++) {            // 512 float4: Q rows
            int idx = tid + i*256;
            int r  = idx >> 2, c4 = idx & 3;
            cp16(&Qs[r*QSTR + c4*4], &Qh[(long long)(s0 + r)*D_ + k0 + c4*4]);
        }
#pragma unroll
        for (int i = 0; i < 2; i++) {            // 512 float4: K rows ([N][K] layout)
            int idx = tid + i*256;
            int r  = idx >> 2, c4 = idx & 3;
            cp16(&Ks[r*KSTR + c4*4], &Kh[(long long)(t0 + r)*D_ + k0 + c4*4]);
        }
    };

    load_tile(0, 0);
    CP_COMMIT();

    const int nk = KD_ / 16;   // 4
#pragma unroll
    for (int kt = 0; kt < nk; kt++) {
        if (kt + 1 < nk) load_tile((kt + 1) & 1, (kt + 1) << 4);
        CP_COMMIT();
        CP_WAIT1();
        __syncthreads();

        const float* Qs = sm + (kt & 1)*SSTAGE;
        const float* Ks = sm + (kt & 1)*SSTAGE + SQTILE;
#pragma unroll
        for (int kk = 0; kk < 16; kk += 8) {
            uint32_t af[2][4], bf[8][2];
#pragma unroll
            for (int mt = 0; mt < 2; mt++) {
                int row = wm*32 + mt*16;
                af[mt][0] = __float_as_uint(Qs[(row + grp    )*QSTR + kk + tig    ]);
                af[mt][1] = __float_as_uint(Qs[(row + grp + 8)*QSTR + kk + tig    ]);
                af[mt][2] = __float_as_uint(Qs[(row + grp    )*QSTR + kk + tig + 4]);
                af[mt][3] = __float_as_uint(Qs[(row + grp + 8)*QSTR + kk + tig + 4]);
            }
#pragma unroll
            for (int nt = 0; nt < 8; nt++) {
                int col = wn*64 + nt*8 + grp;
                bf[nt][0] = __float_as_uint(Ks[col*KSTR + kk + tig    ]);
                bf[nt][1] = __float_as_uint(Ks[col*KSTR + kk + tig + 4]);
            }
#pragma unroll
            for (int mt = 0; mt < 2; mt++)
#pragma unroll
                for (int nt = 0; nt < 8; nt++)
                    mma_tf32(acc[mt][nt], af[mt], bf[nt]);
        }
        __syncthreads();
    }

    // epilogue: mask + scale, write fp32 scores
#pragma unroll
    for (int mt = 0; mt < 2; mt++) {
        int r0 = wm*32 + mt*16 + grp;
#pragma unroll
        for (int nt = 0; nt < 8; nt++) {
            int c = wn*64 + nt*8 + tig*2;
#pragma unroll
            for (int half = 0; half < 2; half++) {
                int s = s0 + r0 + half*8;
                unsigned char pads = padb[s];
                long long base = (long long)s * S_;
#pragma unroll
                for (int q = 0; q < 2; q++) {
                    int t = t0 + c + q;
                    float v = acc[mt][nt][half*2 + q] * 0.125f;
                    bool masked = (t > s) || pads || padb[t];
                    att[base + t] = masked ? -1e30f : v;
                }
            }
        }
    }
}

// ---------------- causal softmax: probs written as tf32 bits -------------------
__global__ void __launch_bounds__(256)
softmax_kernel(float* __restrict__ ATT)
{
    const long long row = blockIdx.x;
    const int s = (int)(row % S_);
    float* p = ATT + row * S_;
    const int tid = threadIdx.x;
    const int L  = s + 1;
    const int Lw = ((s >> 7) + 1) << 7;   // round_up(s+1, 128)

    float v[8];
    float m = -1e30f;
#pragma unroll
    for (int j = 0; j < 8; j++) {
        int i = tid + j*256;
        v[j] = (i < L) ? p[i] : -1e30f;
        m = fmaxf(m, v[j]);
    }
    __shared__ float red[256];
    red[tid] = m; __syncthreads();
    for (int st = 128; st > 0; st >>= 1) {
        if (tid < st) red[tid] = fmaxf(red[tid], red[tid + st]);
        __syncthreads();
    }
    float rowmax = red[0];
    __syncthreads();
    if (rowmax < -1e29f) {                // fully masked row: zero (fixup later)
#pragma unroll
        for (int j = 0; j < 8; j++) {
            int i = tid + j*256;
            if (i < Lw) p[i] = 0.0f;
        }
        return;
    }
    float sum = 0.0f;
#pragma unroll
    for (int j = 0; j < 8; j++) {
        int i = tid + j*256;
        if (i < L) { v[j] = __expf(v[j] - rowmax); sum += v[j]; }
        else v[j] = 0.0f;
    }
    red[tid] = sum; __syncthreads();
    for (int st = 128; st > 0; st >>= 1) {
        if (tid < st) red[tid] += red[tid + st];
        __syncthreads();
    }
    float inv = 1.0f / red[0];
#pragma unroll
    for (int j = 0; j < 8; j++) {
        int i = tid + j*256;
        if (i < L) p[i] = f2tff(v[j] * inv);
        else if (i < Lw) p[i] = 0.0f;
    }
}

// ---------------- layernorm (optional residual add; optional tf32 copy) --------
__global__ void __launch_bounds__(256)
ln_kernel(float* __restrict__ out, float* __restrict__ out32,
          const float* __restrict__ a, const float* __restrict__ r,
          const float* __restrict__ w, const float* __restrict__ bb)
{
    long long base = (long long)blockIdx.x * D_;
    const int tid = threadIdx.x;
    float x[4];
    float sum = 0.0f, sq = 0.0f;
#pragma unroll
    for (int i = 0; i < 4; i++) {
        int c = tid + i*256;
        float v = a[base + c];
        if (r) v += r[base + c];
        x[i] = v; sum += v; sq += v*v;
    }
    __shared__ float r1[256], r2[256];
    r1[tid] = sum; r2[tid] = sq; __syncthreads();
    for (int s = 128; s > 0; s >>= 1) {
        if (tid < s) { r1[tid] += r1[tid + s]; r2[tid] += r2[tid + s]; }
        __syncthreads();
    }
    float mu  = r1[0] * (1.0f / D_);
    float var = r2[0] * (1.0f / D_) - mu*mu;
    float rstd = rsqrtf(var + 1e-5f);
#pragma unroll
    for (int i = 0; i < 4; i++) {
        int c = tid + i*256;
        float o = (x[i] - mu) * rstd * w[c] + bb[c];
        out[base + c] = o;
        if (out32) out32[base + c] = f2tff(o);
    }
}

// ---------------- launch --------------------------------------------------------
extern "C" void kernel_launch(void* const* d_in, const int* in_sizes, int n_in,
                              void* d_out, int out_size)
{
    const float* input = (const float*)d_in[0];
    const void*  mraw  = d_in[1];
    const float* Wq    = (const float*)d_in[2];
    const float* bq    = (const float*)d_in[3];
    const float* Wk    = (const float*)d_in[4];
    const float* bk    = (const float*)d_in[5];
    const float* Wv    = (const float*)d_in[6];
    const float* bv    = (const float*)d_in[7];
    const float* ln1w  = (const float*)d_in[8];
    const float* ln1b  = (const float*)d_in[9];
    const float* ln2w  = (const float*)d_in[10];
    const float* ln2b  = (const float*)d_in[11];
    const float* ff1w  = (const float*)d_in[12];
    const float* ff1b  = (const float*)d_in[13];
    const float* ff2w  = (const float*)d_in[14];
    const float* ff2b  = (const float*)d_in[15];
    float* out = (float*)d_out;

    float *pQ, *pK, *pATT, *pCTX, *pAV, *pX, *pX32, *pFF, *pWq2, *pWk2, *pBvm;
    float *pIN32, *pWv32, *pF1w, *pF2w;
    cudaGetSymbolAddress((void**)&pQ,    g_Q);
    cudaGetSymbolAddress((void**)&pK,    g_K);
    cudaGetSymbolAddress((void**)&pATT,  g_ATT);
    cudaGetSymbolAddress((void**)&pCTX,  g_CTX);
    cudaGetSymbolAddress((void**)&pAV,   g_AV);
    cudaGetSymbolAddress((void**)&pX,    g_X);
    cudaGetSymbolAddress((void**)&pX32,  g_X32);
    cudaGetSymbolAddress((void**)&pFF,   g_FF);
    cudaGetSymbolAddress((void**)&pWq2,  g_Wq2);
    cudaGetSymbolAddress((void**)&pWk2,  g_Wk2);
    cudaGetSymbolAddress((void**)&pBvm,  g_bvm);
    cudaGetSymbolAddress((void**)&pIN32, g_IN32);
    cudaGetSymbolAddress((void**)&pWv32, g_Wv32);
    cudaGetSymbolAddress((void**)&pF1w,  g_ff1w32);
    cudaGetSymbolAddress((void**)&pF2w,  g_ff2w32);

    prep_mask_kernel<<<1, 256>>>(mraw);
    repack_wqk_kernel<<<4096, 256>>>(Wq, Wk);
    bv_mean_kernel<<<4, 256>>>(bv);
    zero_cm_kernel<<<B_*D_/256, 256>>>();
    colsum_kernel<<<B_*32, 256>>>(input);

    // bulk tf32 conversions
    cvt_tf32_kernel<<<(BS_*D_/4 + 255)/256, 256>>>(pIN32, input, BS_*D_/4);
    cvt_tf32_kernel<<<(HD_*D_/4 + 255)/256, 256>>>(pWv32, Wv, HD_*D_/4);
    cvt_tf32_kernel<<<(D_*FF_/4 + 255)/256, 256>>>(pF1w, ff1w, D_*FF_/4);
    cvt_tf32_kernel<<<(FF_*D_/4 + 255)/256, 256>>>(pF2w, ff2w, FF_*D_/4);

    // Q, K projections: [8192,1024] @ [1024,1024], outputs tf32
    mma_gemm<false,false,true><<<dim3(BS_/128, D_/128, 1), 256>>>(
        BS_, D_, D_,
        pIN32, D_, 0LL, 0LL,
        pWq2, D_, 0LL, 0LL,
        pQ, D_, 0LL, 0LL,
        bq, nullptr, 1.0f, 1, 0);
    mma_gemm<false,false,true><<<dim3(BS_/128, D_/128, 1), 256>>>(
        BS_, D_, D_,
        pIN32, D_, 0LL, 0LL,
        pWk2, D_, 0LL, 0LL,
        pK, D_, 0LL, 0LL,
        bk, nullptr, 1.0f, 1, 0);

    // scores (tensor cores, lower tiles only) + causal softmax (writes tf32 probs)
    scores_mma_kernel<<<dim3(S_/128, S_/128, H_*B_), 256>>>(pQ, pK, pATT);
    softmax_kernel<<<H_*B_*S_, 256>>>(pATT);

    // CTX = attn_h,b @ input_b  (tri-truncated K), output tf32; padded-row fixup
    mma_gemm<false,false,true><<<dim3(S_/128, D_/128, H_*B_), 256>>>(
        S_, D_, S_,
        pATT, S_, (long long)B_*S_*S_, (long long)S_*S_,
        pIN32, D_, 0LL, (long long)S_*D_,
        pCTX, HD_, (long long)D_, (long long)S_*HD_,
        nullptr, nullptr, 1.0f, B_, 1 /*tri*/);
    ctx_fixup_kernel<<<BS_, 256>>>();

    // AV = CTX[8192,16384] @ Wv_flat[16384,1024] / H + mean bias (fp32 out)
    mma_gemm<false,false,false><<<dim3(BS_/128, D_/128, 1), 256>>>(
        BS_, D_, HD_,
        pCTX, HD_, 0LL, 0LL,
        pWv32, D_, 0LL, 0LL,
        pAV, D_, 0LL, 0LL,
        pBvm, nullptr, 1.0f/H_, 1, 0);

    // x = LN1(input + AV); fp32 + tf32 copies
    ln_kernel<<<BS_, 256>>>(pX, pX32, input, pAV, ln1w, ln1b);

    // FFN
    mma_gemm<true,false,true><<<dim3(BS_/128, FF_/128, 1), 256>>>(
        BS_, FF_, D_,
        pX32, D_, 0LL, 0LL,
        pF1w, FF_, 0LL, 0LL,
        pFF, FF_, 0LL, 0LL,
        ff1b, nullptr, 1.0f, 1, 0);
    mma_gemm<false,true,false><<<dim3(BS_/128, D_/128, 1), 256>>>(
        BS_, D_, FF_,
        pFF, FF_, 0LL, 0LL,
        pF2w, D_, 0LL, 0LL,
        pAV, D_, 0LL, 0LL,
        ff2b, pX, 1.0f, 1, 0);

    // out = LN2(x + ff)
    ln_kernel<<<BS_, 256>>>(out, nullptr, pAV, nullptr, ln2w, ln2b);
}

// round 9
// speedup vs baseline: 5.4729x; 1.0704x over previous
#include <cuda_runtime.h>
#include <math.h>
#include <stdint.h>

#define B_   4
#define S_   2048
#define D_   1024
#define H_   16
#define KD_  64
#define FF_  4096
#define BS_  (B_*S_)   // 8192
#define HD_  (H_*D_)   // 16384

// ---------------- scratch (static device globals; no allocations) -------------
__device__ float g_Q  [BS_*D_];                     // Q proj, tf32 bits
__device__ float g_K  [BS_*D_];                     // K proj, tf32 bits
__device__ float g_ATT[(size_t)H_*B_*S_*S_];        // scores fp32 -> probs tf32
__device__ float g_CTX[(size_t)BS_*HD_];            // per-head contexts, tf32 bits
__device__ float g_AV [BS_*D_];                     // attention_values / ffn2 out (fp32)
__device__ float g_X  [BS_*D_];                     // ln1 output fp32
__device__ float g_X32[BS_*D_];                     // ln1 output tf32 bits
__device__ float g_FF [BS_*FF_];                    // ffn hidden, tf32 bits
__device__ float g_Wq2[D_*D_];                      // repacked Wq, tf32
__device__ float g_Wk2[D_*D_];                      // repacked Wk, tf32
__device__ float g_IN32 [BS_*D_];                   // input, tf32 bits
__device__ float g_Wv32 [HD_*D_];                   // Wv flat, tf32 bits
__device__ float g_ff1w32[D_*FF_];                  // ff1w, tf32 bits
__device__ float g_ff2w32[FF_*D_];                  // ff2w, tf32 bits
__device__ float g_bvm[D_];                         // mean_h bv / H (fp32)
__device__ float g_cm [B_*D_];                      // column sums of input per batch
__device__ unsigned char g_pad[BS_];                // normalized padding mask

__device__ __forceinline__ uint32_t f2tf(float f)
{
    uint32_t r;
    asm("cvt.rna.tf32.f32 %0, %1;" : "=r"(r) : "f"(f));
    return r;
}
__device__ __forceinline__ float f2tff(float f) { return __uint_as_float(f2tf(f)); }

// ---------------- padding-mask dtype detection + normalization ----------------
__global__ void prep_mask_kernel(const void* raw)
{
    const unsigned char* bytes = (const unsigned char*)raw;
    __shared__ int sFloat, sOff, sAny;
    if (threadIdx.x == 0) { sFloat = 0; sOff = 0; sAny = 0; }
    __syncthreads();
    int lf = 0, lo = 0, la = 0;
    for (int i = threadIdx.x; i < BS_; i += blockDim.x) {
        unsigned char c = bytes[i];
        if (c) la = 1;
        if (c > 1) lf = 1;
        if ((i & 3) && c) lo = 1;
    }
    if (lf) atomicOr(&sFloat, 1);
    if (lo) atomicOr(&sOff, 1);
    if (la) atomicOr(&sAny, 1);
    __syncthreads();
    int mode;
    if (!sAny)       mode = 3;
    else if (sFloat) mode = 2;
    else if (sOff)   mode = 0;
    else             mode = 1;
    for (int i = threadIdx.x; i < BS_; i += blockDim.x) {
        unsigned char p;
        if (mode == 3)      p = 0;
        else if (mode == 2) p = (((const float*)raw)[i] != 0.0f);
        else if (mode == 1) p = (((const int*)raw)[i]   != 0);
        else                p = (bytes[i] != 0);
        g_pad[i] = p;
    }
}

// ---------------- fp32 -> tf32-bits bulk convert -------------------------------
__global__ void cvt_tf32_kernel(float* __restrict__ dst, const float* __restrict__ src,
                                int n4)
{
    int i = blockIdx.x * 256 + threadIdx.x;
    if (i >= n4) return;
    float4 v = ((const float4*)src)[i];
    v.x = f2tff(v.x); v.y = f2tff(v.y); v.z = f2tff(v.z); v.w = f2tff(v.w);
    ((float4*)dst)[i] = v;
}

// ---------------- weight repack: Wq[h][d][k] -> Wq2[d][h*64+k] (tf32) ----------
__global__ void repack_wqk_kernel(const float* __restrict__ Wq,
                                  const float* __restrict__ Wk)
{
    int i = blockIdx.x * 256 + threadIdx.x;      // over H*D*KD = 2^20
    int k = i & 63;
    int d = (i >> 6) & 1023;
    int h = i >> 16;
    g_Wq2[d*D_ + h*KD_ + k] = f2tff(Wq[i]);
    g_Wk2[d*D_ + h*KD_ + k] = f2tff(Wk[i]);
}

__global__ void bv_mean_kernel(const float* __restrict__ bv)
{
    int e = blockIdx.x * 256 + threadIdx.x;
    float s = 0.0f;
#pragma unroll
    for (int h = 0; h < H_; h++) s += bv[h*D_ + e];
    g_bvm[e] = s * (1.0f / H_);
}

// ---------------- column sums of input (for padded-row fixup) ------------------
__global__ void zero_cm_kernel()
{
    g_cm[blockIdx.x * 256 + threadIdx.x] = 0.0f;
}
__global__ void colsum_kernel(const float* __restrict__ input)
{
    int b  = blockIdx.x >> 5;
    int tc = blockIdx.x & 31;
    int e4 = threadIdx.x * 4;
    const float* base = input + (long long)b*S_*D_ + (long long)tc*64*D_;
    float4 s = make_float4(0.f, 0.f, 0.f, 0.f);
    for (int t = 0; t < 64; t++) {
        float4 v = *(const float4*)&base[(long long)t*D_ + e4];
        s.x += v.x; s.y += v.y; s.z += v.z; s.w += v.w;
    }
    atomicAdd(&g_cm[b*D_ + e4 + 0], s.x);
    atomicAdd(&g_cm[b*D_ + e4 + 1], s.y);
    atomicAdd(&g_cm[b*D_ + e4 + 2], s.z);
    atomicAdd(&g_cm[b*D_ + e4 + 3], s.w);
}
// padded rows: CTX[row][(h,e)] = colmean(input_b)[e] for all heads (tf32 bits)
__global__ void ctx_fixup_kernel()
{
    int row = blockIdx.x;
    if (!g_pad[row]) return;
    int b = row / S_;
    int e = threadIdx.x * 4;
    float4 v = *(const float4*)&g_cm[b*D_ + e];
    const float inv = 1.0f / (float)S_;
    v.x = f2tff(v.x * inv); v.y = f2tff(v.y * inv);
    v.z = f2tff(v.z * inv); v.w = f2tff(v.w * inv);
    float* dst = g_CTX + (size_t)row * HD_;
#pragma unroll
    for (int h = 0; h < H_; h++)
        *(float4*)&dst[h*D_ + e] = v;
}

// ---------------- cp.async helpers ---------------------------------------------
__device__ __forceinline__ void cp16(void* smem, const void* g)
{
    uint32_t s = (uint32_t)__cvta_generic_to_shared(smem);
    asm volatile("cp.async.cg.shared.global [%0], [%1], 16;\n" :: "r"(s), "l"(g));
}
#define CP_COMMIT() asm volatile("cp.async.commit_group;\n" ::)
#define CP_WAIT1()  asm volatile("cp.async.wait_group 1;\n" ::)

__device__ __forceinline__ void mma_tf32(float* d, const uint32_t* a, const uint32_t* b)
{
    asm volatile(
        "mma.sync.aligned.m16n8k8.row.col.f32.tf32.tf32.f32 "
        "{%0,%1,%2,%3},{%4,%5,%6,%7},{%8,%9},{%0,%1,%2,%3};"
        : "+f"(d[0]), "+f"(d[1]), "+f"(d[2]), "+f"(d[3])
        : "r"(a[0]), "r"(a[1]), "r"(a[2]), "r"(a[3]), "r"(b[0]), "r"(b[1]));
}

// ---------------- tf32 tensor-core GEMM (static smem, BK=16, 2-stage) ----------
// 128 threads, 4 warps in 2x2, warp tile 64x64 -> 1.0 LDS per MMA
#define ASTRIDE 24          // 16 + 8 pad (floats)
#define BSTRIDE 136         // 128 + 8 pad
#define ATILE (128*ASTRIDE)
#define BTILE (16*BSTRIDE)
#define STAGEF (ATILE + BTILE) // 21KB per stage; 2 stages = 42KB static

// C = alpha*(A@B) [+bias] [relu] [+resid]; tri => K truncated to m0+128
template<bool RELU, bool RESID, bool OUTTF>
__global__ void __launch_bounds__(128)
mma_gemm(int M, int N, int K,
         const float* __restrict__ A, int lda, long long sAh, long long sAb,
         const float* __restrict__ Bm, int ldb, long long sBh, long long sBb,
         float* __restrict__ C, int ldc, long long sCh, long long sCb,
         const float* __restrict__ bias, const float* __restrict__ resid,
         float alpha, int zB, int tri)
{
    __shared__ float sm[2*STAGEF];
    const int tid = threadIdx.x;
    const int z = blockIdx.z;
    const int zh = z / zB, zb = z % zB;
    A    += zh*sAh + zb*sAb;
    Bm   += zh*sBh + zb*sBb;
    long long coff = zh*sCh + zb*sCb;
    C    += coff;
    const float* res = RESID ? (resid + coff) : nullptr;

    const int m0 = blockIdx.x * 128;
    const int n0 = blockIdx.y * 128;

    const int warp = tid >> 5, lane = tid & 31;
    const int wm = warp >> 1, wn = warp & 1;     // 2x2 warps, warp tile 64x64
    const int grp = lane >> 2, tig = lane & 3;

    float acc[4][8][4];
#pragma unroll
    for (int i = 0; i < 4; i++)
#pragma unroll
        for (int j = 0; j < 8; j++)
#pragma unroll
            for (int k = 0; k < 4; k++) acc[i][j][k] = 0.0f;

    int Ke = tri ? (m0 + 128 < K ? m0 + 128 : K) : K;
    const int nk = Ke >> 4;   // K/16

    auto load_tile = [&](int st, int k0) {
        float* As = sm + st*STAGEF;
        float* Bs = sm + st*STAGEF + ATILE;
#pragma unroll
        for (int i = 0; i < 4; i++) {            // 512 float4 for A (128x16)
            int idx = tid + i*128;
            int r  = idx >> 2, c4 = idx & 3;
            cp16(&As[r*ASTRIDE + c4*4], &A[(long long)(m0 + r)*lda + k0 + c4*4]);
        }
#pragma unroll
        for (int i = 0; i < 4; i++) {            // 512 float4 for B (16x128)
            int idx = tid + i*128;
            int r  = idx >> 5, c4 = idx & 31;
            cp16(&Bs[r*BSTRIDE + c4*4], &Bm[(long long)(k0 + r)*ldb + n0 + c4*4]);
        }
    };

    load_tile(0, 0);
    CP_COMMIT();

    for (int kt = 0; kt < nk; kt++) {
        if (kt + 1 < nk) load_tile((kt + 1) & 1, (kt + 1) << 4);
        CP_COMMIT();
        CP_WAIT1();
        __syncthreads();

        const float* As = sm + (kt & 1)*STAGEF;
        const float* Bs = sm + (kt & 1)*STAGEF + ATILE;
#pragma unroll
        for (int kk = 0; kk < 16; kk += 8) {
            uint32_t af[4][4], bf[8][2];
#pragma unroll
            for (int mt = 0; mt < 4; mt++) {
                int row = wm*64 + mt*16;
                af[mt][0] = __float_as_uint(As[(row + grp    )*ASTRIDE + kk + tig    ]);
                af[mt][1] = __float_as_uint(As[(row + grp + 8)*ASTRIDE + kk + tig    ]);
                af[mt][2] = __float_as_uint(As[(row + grp    )*ASTRIDE + kk + tig + 4]);
                af[mt][3] = __float_as_uint(As[(row + grp + 8)*ASTRIDE + kk + tig + 4]);
            }
#pragma unroll
            for (int nt = 0; nt < 8; nt++) {
                int col = wn*64 + nt*8 + grp;
                bf[nt][0] = __float_as_uint(Bs[(kk + tig    )*BSTRIDE + col]);
                bf[nt][1] = __float_as_uint(Bs[(kk + tig + 4)*BSTRIDE + col]);
            }
#pragma unroll
            for (int mt = 0; mt < 4; mt++)
#pragma unroll
                for (int nt = 0; nt < 8; nt++)
                    mma_tf32(acc[mt][nt], af[mt], bf[nt]);
        }
        __syncthreads();
    }

#pragma unroll
    for (int mt = 0; mt < 4; mt++) {
        int r0 = m0 + wm*64 + mt*16 + grp;
#pragma unroll
        for (int nt = 0; nt < 8; nt++) {
            int c = n0 + wn*64 + nt*8 + tig*2;
            float v00 = acc[mt][nt][0]*alpha, v01 = acc[mt][nt][1]*alpha;
            float v10 = acc[mt][nt][2]*alpha, v11 = acc[mt][nt][3]*alpha;
            if (bias) {
                float2 bv2 = *(const float2*)&bias[c];
                v00 += bv2.x; v01 += bv2.y; v10 += bv2.x; v11 += bv2.y;
            }
            if (RELU) {
                v00 = fmaxf(v00, 0.0f); v01 = fmaxf(v01, 0.0f);
                v10 = fmaxf(v10, 0.0f); v11 = fmaxf(v11, 0.0f);
            }
            long long i0 = (long long)r0*ldc + c;
            long long i1 = (long long)(r0 + 8)*ldc + c;
            if (RESID) {
                float2 e0 = *(const float2*)&res[i0];
                float2 e1 = *(const float2*)&res[i1];
                v00 += e0.x; v01 += e0.y; v10 += e1.x; v11 += e1.y;
            }
            if (OUTTF) {
                v00 = f2tff(v00); v01 = f2tff(v01);
                v10 = f2tff(v10); v11 = f2tff(v11);
            }
            *(float2*)&C[i0] = make_float2(v00, v01);
            *(float2*)&C[i1] = make_float2(v10, v11);
        }
    }
}

// ---------------- scores on tensor cores: Q @ K^T / 8, lower tiles only --------
#define QSTR 24             // A tile stride (16+8)
#define KSTR 20             // B tile stride (16+4)
#define SQTILE (128*QSTR)
#define SKTILE (128*KSTR)
#define SSTAGE (SQTILE + SKTILE)

__global__ void __launch_bounds__(256)
scores_mma_kernel(const float* __restrict__ Q, const float* __restrict__ Kc,
                  float* __restrict__ ATT)
{
    const int s0 = blockIdx.x * 128;
    const int t0 = blockIdx.y * 128;
    if (t0 > s0) return;               // strictly-upper tile: never read downstream

    __shared__ float sm[2*SSTAGE];
    const int z = blockIdx.z;          // h*B + b
    const int b = z % B_;
    const int h = z / B_;
    float* att = ATT + (long long)z * S_ * S_;
    const int tid = threadIdx.x;

    const float* Qh = Q  + (long long)(b*S_)*D_ + h*KD_;
    const float* Kh = Kc + (long long)(b*S_)*D_ + h*KD_;
    const unsigned char* padb = g_pad + b*S_;

    const int warp = tid >> 5, lane = tid & 31;
    const int wm = warp >> 1, wn = warp & 1;
    const int grp = lane >> 2, tig = lane & 3;

    float acc[2][8][4];
#pragma unroll
    for (int i = 0; i < 2; i++)
#pragma unroll
        for (int j = 0; j < 8; j++)
#pragma unroll
            for (int k = 0; k < 4; k++) acc[i][j][k] = 0.0f;

    auto load_tile = [&](int st, int k0) {
        float* Qs = sm + st*SSTAGE;
        float* Ks = sm + st*SSTAGE + SQTILE;
#pragma unroll
        for (int i = 0; i < 2; i++) {
            int idx = tid + i*256;
            int r  = idx >> 2, c4 = idx & 3;
            cp16(&Qs[r*QSTR + c4*4], &Qh[(long long)(s0 + r)*D_ + k0 + c4*4]);
        }
#pragma unroll
        for (int i = 0; i < 2; i++) {
            int idx = tid + i*256;
            int r  = idx >> 2, c4 = idx & 3;
            cp16(&Ks[r*KSTR + c4*4], &Kh[(long long)(t0 + r)*D_ + k0 + c4*4]);
        }
    };

    load_tile(0, 0);
    CP_COMMIT();

    const int nk = KD_ / 16;   // 4
#pragma unroll
    for (int kt = 0; kt < nk; kt++) {
        if (kt + 1 < nk) load_tile((kt + 1) & 1, (kt + 1) << 4);
        CP_COMMIT();
        CP_WAIT1();
        __syncthreads();

        const float* Qs = sm + (kt & 1)*SSTAGE;
        const float* Ks = sm + (kt & 1)*SSTAGE + SQTILE;
#pragma unroll
        for (int kk = 0; kk < 16; kk += 8) {
            uint32_t af[2][4], bf[8][2];
#pragma unroll
            for (int mt = 0; mt < 2; mt++) {
                int row = wm*32 + mt*16;
                af[mt][0] = __float_as_uint(Qs[(row + grp    )*QSTR + kk + tig    ]);
                af[mt][1] = __float_as_uint(Qs[(row + grp + 8)*QSTR + kk + tig    ]);
                af[mt][2] = __float_as_uint(Qs[(row + grp    )*QSTR + kk + tig + 4]);
                af[mt][3] = __float_as_uint(Qs[(row + grp + 8)*QSTR + kk + tig + 4]);
            }
#pragma unroll
            for (int nt = 0; nt < 8; nt++) {
                int col = wn*64 + nt*8 + grp;
                bf[nt][0] = __float_as_uint(Ks[col*KSTR + kk + tig    ]);
                bf[nt][1] = __float_as_uint(Ks[col*KSTR + kk + tig + 4]);
            }
#pragma unroll
            for (int mt = 0; mt < 2; mt++)
#pragma unroll
                for (int nt = 0; nt < 8; nt++)
                    mma_tf32(acc[mt][nt], af[mt], bf[nt]);
        }
        __syncthreads();
    }

    // epilogue: mask + scale, write fp32 scores
#pragma unroll
    for (int mt = 0; mt < 2; mt++) {
        int r0 = wm*32 + mt*16 + grp;
#pragma unroll
        for (int nt = 0; nt < 8; nt++) {
            int c = wn*64 + nt*8 + tig*2;
#pragma unroll
            for (int half = 0; half < 2; half++) {
                int s = s0 + r0 + half*8;
                unsigned char pads = padb[s];
                long long base = (long long)s * S_;
#pragma unroll
                for (int q = 0; q < 2; q++) {
                    int t = t0 + c + q;
                    float v = acc[mt][nt][half*2 + q] * 0.125f;
                    bool masked = (t > s) || pads || padb[t];
                    att[base + t] = masked ? -1e30f : v;
                }
            }
        }
    }
}

// ---------------- causal softmax: probs written as tf32 bits -------------------
__global__ void __launch_bounds__(256)
softmax_kernel(float* __restrict__ ATT)
{
    const long long row = blockIdx.x;
    const int s = (int)(row % S_);
    float* p = ATT + row * S_;
    const int tid = threadIdx.x;
    const int L  = s + 1;
    const int Lw = ((s >> 7) + 1) << 7;   // round_up(s+1, 128)

    float v[8];
    float m = -1e30f;
#pragma unroll
    for (int j = 0; j < 8; j++) {
        int i = tid + j*256;
        v[j] = (i < L) ? p[i] : -1e30f;
        m = fmaxf(m, v[j]);
    }
    __shared__ float red[256];
    red[tid] = m; __syncthreads();
    for (int st = 128; st > 0; st >>= 1) {
        if (tid < st) red[tid] = fmaxf(red[tid], red[tid + st]);
        __syncthreads();
    }
    float rowmax = red[0];
    __syncthreads();
    if (rowmax < -1e29f) {                // fully masked row: zero (fixup later)
#pragma unroll
        for (int j = 0; j < 8; j++) {
            int i = tid + j*256;
            if (i < Lw) p[i] = 0.0f;
        }
        return;
    }
    float sum = 0.0f;
#pragma unroll
    for (int j = 0; j < 8; j++) {
        int i = tid + j*256;
        if (i < L) { v[j] = __expf(v[j] - rowmax); sum += v[j]; }
        else v[j] = 0.0f;
    }
    red[tid] = sum; __syncthreads();
    for (int st = 128; st > 0; st >>= 1) {
        if (tid < st) red[tid] += red[tid + st];
        __syncthreads();
    }
    float inv = 1.0f / red[0];
#pragma unroll
    for (int j = 0; j < 8; j++) {
        int i = tid + j*256;
        if (i < L) p[i] = f2tff(v[j] * inv);
        else if (i < Lw) p[i] = 0.0f;
    }
}

// ---------------- layernorm (optional residual add; optional tf32 copy) --------
__global__ void __launch_bounds__(256)
ln_kernel(float* __restrict__ out, float* __restrict__ out32,
          const float* __restrict__ a, const float* __restrict__ r,
          const float* __restrict__ w, const float* __restrict__ bb)
{
    long long base = (long long)blockIdx.x * D_;
    const int tid = threadIdx.x;
    float x[4];
    float sum = 0.0f, sq = 0.0f;
#pragma unroll
    for (int i = 0; i < 4; i++) {
        int c = tid + i*256;
        float v = a[base + c];
        if (r) v += r[base + c];
        x[i] = v; sum += v; sq += v*v;
    }
    __shared__ float r1[256], r2[256];
    r1[tid] = sum; r2[tid] = sq; __syncthreads();
    for (int s = 128; s > 0; s >>= 1) {
        if (tid < s) { r1[tid] += r1[tid + s]; r2[tid] += r2[tid + s]; }
        __syncthreads();
    }
    float mu  = r1[0] * (1.0f / D_);
    float var = r2[0] * (1.0f / D_) - mu*mu;
    float rstd = rsqrtf(var + 1e-5f);
#pragma unroll
    for (int i = 0; i < 4; i++) {
        int c = tid + i*256;
        float o = (x[i] - mu) * rstd * w[c] + bb[c];
        out[base + c] = o;
        if (out32) out32[base + c] = f2tff(o);
    }
}

// ---------------- launch --------------------------------------------------------
extern "C" void kernel_launch(void* const* d_in, const int* in_sizes, int n_in,
                              void* d_out, int out_size)
{
    const float* input = (const float*)d_in[0];
    const void*  mraw  = d_in[1];
    const float* Wq    = (const float*)d_in[2];
    const float* bq    = (const float*)d_in[3];
    const float* Wk    = (const float*)d_in[4];
    const float* bk    = (const float*)d_in[5];
    const float* Wv    = (const float*)d_in[6];
    const float* bv    = (const float*)d_in[7];
    const float* ln1w  = (const float*)d_in[8];
    const float* ln1b  = (const float*)d_in[9];
    const float* ln2w  = (const float*)d_in[10];
    const float* ln2b  = (const float*)d_in[11];
    const float* ff1w  = (const float*)d_in[12];
    const float* ff1b  = (const float*)d_in[13];
    const float* ff2w  = (const float*)d_in[14];
    const float* ff2b  = (const float*)d_in[15];
    float* out = (float*)d_out;

    float *pQ, *pK, *pATT, *pCTX, *pAV, *pX, *pX32, *pFF, *pWq2, *pWk2, *pBvm;
    float *pIN32, *pWv32, *pF1w, *pF2w;
    cudaGetSymbolAddress((void**)&pQ,    g_Q);
    cudaGetSymbolAddress((void**)&pK,    g_K);
    cudaGetSymbolAddress((void**)&pATT,  g_ATT);
    cudaGetSymbolAddress((void**)&pCTX,  g_CTX);
    cudaGetSymbolAddress((void**)&pAV,   g_AV);
    cudaGetSymbolAddress((void**)&pX,    g_X);
    cudaGetSymbolAddress((void**)&pX32,  g_X32);
    cudaGetSymbolAddress((void**)&pFF,   g_FF);
    cudaGetSymbolAddress((void**)&pWq2,  g_Wq2);
    cudaGetSymbolAddress((void**)&pWk2,  g_Wk2);
    cudaGetSymbolAddress((void**)&pBvm,  g_bvm);
    cudaGetSymbolAddress((void**)&pIN32, g_IN32);
    cudaGetSymbolAddress((void**)&pWv32, g_Wv32);
    cudaGetSymbolAddress((void**)&pF1w,  g_ff1w32);
    cudaGetSymbolAddress((void**)&pF2w,  g_ff2w32);

    prep_mask_kernel<<<1, 256>>>(mraw);
    repack_wqk_kernel<<<4096, 256>>>(Wq, Wk);
    bv_mean_kernel<<<4, 256>>>(bv);
    zero_cm_kernel<<<B_*D_/256, 256>>>();
    colsum_kernel<<<B_*32, 256>>>(input);

    // bulk tf32 conversions
    cvt_tf32_kernel<<<(BS_*D_/4 + 255)/256, 256>>>(pIN32, input, BS_*D_/4);
    cvt_tf32_kernel<<<(HD_*D_/4 + 255)/256, 256>>>(pWv32, Wv, HD_*D_/4);
    cvt_tf32_kernel<<<(D_*FF_/4 + 255)/256, 256>>>(pF1w, ff1w, D_*FF_/4);
    cvt_tf32_kernel<<<(FF_*D_/4 + 255)/256, 256>>>(pF2w, ff2w, FF_*D_/4);

    // Q, K projections: [8192,1024] @ [1024,1024], outputs tf32
    mma_gemm<false,false,true><<<dim3(BS_/128, D_/128, 1), 128>>>(
        BS_, D_, D_,
        pIN32, D_, 0LL, 0LL,
        pWq2, D_, 0LL, 0LL,
        pQ, D_, 0LL, 0LL,
        bq, nullptr, 1.0f, 1, 0);
    mma_gemm<false,false,true><<<dim3(BS_/128, D_/128, 1), 128>>>(
        BS_, D_, D_,
        pIN32, D_, 0LL, 0LL,
        pWk2, D_, 0LL, 0LL,
        pK, D_, 0LL, 0LL,
        bk, nullptr, 1.0f, 1, 0);

    // scores (tensor cores, lower tiles only) + causal softmax (tf32 probs)
    scores_mma_kernel<<<dim3(S_/128, S_/128, H_*B_), 256>>>(pQ, pK, pATT);
    softmax_kernel<<<H_*B_*S_, 256>>>(pATT);

    // CTX = attn_h,b @ input_b  (tri-truncated K), output tf32; padded-row fixup
    mma_gemm<false,false,true><<<dim3(S_/128, D_/128, H_*B_), 128>>>(
        S_, D_, S_,
        pATT, S_, (long long)B_*S_*S_, (long long)S_*S_,
        pIN32, D_, 0LL, (long long)S_*D_,
        pCTX, HD_, (long long)D_, (long long)S_*HD_,
        nullptr, nullptr, 1.0f, B_, 1 /*tri*/);
    ctx_fixup_kernel<<<BS_, 256>>>();

    // AV = CTX[8192,16384] @ Wv_flat[16384,1024] / H + mean bias (fp32 out)
    mma_gemm<false,false,false><<<dim3(BS_/128, D_/128, 1), 128>>>(
        BS_, D_, HD_,
        pCTX, HD_, 0LL, 0LL,
        pWv32, D_, 0LL, 0LL,
        pAV, D_, 0LL, 0LL,
        pBvm, nullptr, 1.0f/H_, 1, 0);

    // x = LN1(input + AV); fp32 + tf32 copies
    ln_kernel<<<BS_, 256>>>(pX, pX32, input, pAV, ln1w, ln1b);

    // FFN
    mma_gemm<true,false,true><<<dim3(BS_/128, FF_/128, 1), 128>>>(
        BS_, FF_, D_,
        pX32, D_, 0LL, 0LL,
        pF1w, FF_, 0LL, 0LL,
        pFF, FF_, 0LL, 0LL,
        ff1b, nullptr, 1.0f, 1, 0);
    mma_gemm<false,true,false><<<dim3(BS_/128, D_/128, 1), 128>>>(
        BS_, D_, FF_,
        pFF, FF_, 0LL, 0LL,
        pF2w, D_, 0LL, 0LL,
        pAV, D_, 0LL, 0LL,
        ff2b, pX, 1.0f, 1, 0);

    // out = LN2(x + ff)
    ln_kernel<<<BS_, 256>>>(out, nullptr, pAV, nullptr, ln2w, ln2b);
}

// round 10
// speedup vs baseline: 5.4951x; 1.0041x over previous
#include <cuda_runtime.h>
#include <math.h>
#include <stdint.h>

#define B_   4
#define S_   2048
#define D_   1024
#define H_   16
#define KD_  64
#define FF_  4096
#define BS_  (B_*S_)   // 8192
#define HD_  (H_*D_)   // 16384
#define QKN  (2*D_)    // 2048

// ---------------- scratch (static device globals; no allocations) -------------
__device__ float g_QK [BS_*QKN];                    // [s][ Q(h,kd) | K(h,kd) ], tf32
__device__ float g_ATT[(size_t)H_*B_*S_*S_];        // scores fp32 -> probs tf32
__device__ float g_CTX[(size_t)BS_*HD_];            // per-head contexts, tf32 bits
__device__ float g_AV [BS_*D_];                     // attention_values / ffn2 out (fp32)
__device__ float g_X  [BS_*D_];                     // ln1 output fp32
__device__ float g_X32[BS_*D_];                     // ln1 output tf32 bits
__device__ float g_FF [BS_*FF_];                    // ffn hidden, tf32 bits
__device__ float g_Wqk2[D_*QKN];                    // repacked [Wq|Wk], tf32
__device__ float g_IN32 [BS_*D_];                   // input, tf32 bits
__device__ float g_Wv32 [HD_*D_];                   // Wv flat, tf32 bits
__device__ float g_ff1w32[D_*FF_];                  // ff1w, tf32 bits
__device__ float g_ff2w32[FF_*D_];                  // ff2w, tf32 bits
__device__ float g_bqk[QKN];                        // [bq|bk]
__device__ float g_bvm[D_];                         // mean_h bv / H (fp32)
__device__ float g_cm [B_*D_];                      // column sums of input per batch
__device__ unsigned char g_pad[BS_];                // normalized padding mask

__device__ __forceinline__ uint32_t f2tf(float f)
{
    uint32_t r;
    asm("cvt.rna.tf32.f32 %0, %1;" : "=r"(r) : "f"(f));
    return r;
}
__device__ __forceinline__ float f2tff(float f) { return __uint_as_float(f2tf(f)); }

// ---------------- launch 1: padding-mask dtype detection + normalization -------
__global__ void prep_mask_kernel(const void* raw)
{
    const unsigned char* bytes = (const unsigned char*)raw;
    __shared__ int sFloat, sOff, sAny;
    if (threadIdx.x == 0) { sFloat = 0; sOff = 0; sAny = 0; }
    __syncthreads();
    int lf = 0, lo = 0, la = 0;
    for (int i = threadIdx.x; i < BS_; i += blockDim.x) {
        unsigned char c = bytes[i];
        if (c) la = 1;
        if (c > 1) lf = 1;
        if ((i & 3) && c) lo = 1;
    }
    if (lf) atomicOr(&sFloat, 1);
    if (lo) atomicOr(&sOff, 1);
    if (la) atomicOr(&sAny, 1);
    __syncthreads();
    int mode;
    if (!sAny)       mode = 3;
    else if (sFloat) mode = 2;
    else if (sOff)   mode = 0;
    else             mode = 1;
    for (int i = threadIdx.x; i < BS_; i += blockDim.x) {
        unsigned char p;
        if (mode == 3)      p = 0;
        else if (mode == 2) p = (((const float*)raw)[i] != 0.0f);
        else if (mode == 1) p = (((const int*)raw)[i]   != 0);
        else                p = (bytes[i] != 0);
        g_pad[i] = p;
    }
}

// ---------------- launch 2: Wq/Wk -> combined [d][ h*64+k | 1024 + h*64+k ] ----
__global__ void repack_wqk_kernel(const float* __restrict__ Wq,
                                  const float* __restrict__ Wk)
{
    int i = blockIdx.x * 256 + threadIdx.x;      // over H*D*KD = 2^20
    int k = i & 63;
    int d = (i >> 6) & 1023;
    int h = i >> 16;
    g_Wqk2[d*QKN + h*KD_ + k]       = f2tff(Wq[i]);
    g_Wqk2[d*QKN + D_ + h*KD_ + k]  = f2tff(Wk[i]);
}

// ---------------- launch 3: all fp32->tf32 bulk conversions + bias concat ------
#define N4_IN  (BS_*D_/4)      // 2097152
#define N4_WV  (HD_*D_/4)      // 4194304
#define N4_F1  (D_*FF_/4)      // 1048576
#define N4_F2  (FF_*D_/4)      // 1048576
__global__ void cvt_all_kernel(const float* __restrict__ input,
                               const float* __restrict__ Wv,
                               const float* __restrict__ ff1w,
                               const float* __restrict__ ff2w,
                               const float* __restrict__ bq,
                               const float* __restrict__ bk)
{
    int i = blockIdx.x * 256 + threadIdx.x;
    if (i < D_) {                      // bias concat (first 4 blocks)
        g_bqk[i]      = bq[i];
        g_bqk[D_ + i] = bk[i];
    }
    const float* src; float* dst; int j = i;
    if (j < N4_IN) { src = input; dst = g_IN32; }
    else if ((j -= N4_IN) < N4_WV) { src = Wv; dst = g_Wv32; }
    else if ((j -= N4_WV) < N4_F1) { src = ff1w; dst = g_ff1w32; }
    else { j -= N4_F1; src = ff2w; dst = g_ff2w32; }
    float4 v = ((const float4*)src)[j];
    v.x = f2tff(v.x); v.y = f2tff(v.y); v.z = f2tff(v.z); v.w = f2tff(v.w);
    ((float4*)dst)[j] = v;
}

// ---------------- launch 7: zero colsum accum + bv mean ------------------------
__global__ void misc_kernel(const float* __restrict__ bv)
{
    int i = blockIdx.x * 256 + threadIdx.x;      // 0..4095
    g_cm[i] = 0.0f;
    if (i < D_) {
        float s = 0.0f;
#pragma unroll
        for (int h = 0; h < H_; h++) s += bv[h*D_ + i];
        g_bvm[i] = s * (1.0f / H_);
    }
}

// ---------------- launch 8: column sums of input -------------------------------
__global__ void colsum_kernel(const float* __restrict__ input)
{
    int b  = blockIdx.x >> 5;
    int tc = blockIdx.x & 31;
    int e4 = threadIdx.x * 4;
    const float* base = input + (long long)b*S_*D_ + (long long)tc*64*D_;
    float4 s = make_float4(0.f, 0.f, 0.f, 0.f);
    for (int t = 0; t < 64; t++) {
        float4 v = *(const float4*)&base[(long long)t*D_ + e4];
        s.x += v.x; s.y += v.y; s.z += v.z; s.w += v.w;
    }
    atomicAdd(&g_cm[b*D_ + e4 + 0], s.x);
    atomicAdd(&g_cm[b*D_ + e4 + 1], s.y);
    atomicAdd(&g_cm[b*D_ + e4 + 2], s.z);
    atomicAdd(&g_cm[b*D_ + e4 + 3], s.w);
}
// padded rows: CTX[row][(h,e)] = colmean(input_b)[e] for all heads (tf32 bits)
__global__ void ctx_fixup_kernel()
{
    int row = blockIdx.x;
    if (!g_pad[row]) return;
    int b = row / S_;
    int e = threadIdx.x * 4;
    float4 v = *(const float4*)&g_cm[b*D_ + e];
    const float inv = 1.0f / (float)S_;
    v.x = f2tff(v.x * inv); v.y = f2tff(v.y * inv);
    v.z = f2tff(v.z * inv); v.w = f2tff(v.w * inv);
    float* dst = g_CTX + (size_t)row * HD_;
#pragma unroll
    for (int h = 0; h < H_; h++)
        *(float4*)&dst[h*D_ + e] = v;
}

// ---------------- cp.async helpers ---------------------------------------------
__device__ __forceinline__ void cp16(void* smem, const void* g)
{
    uint32_t s = (uint32_t)__cvta_generic_to_shared(smem);
    asm volatile("cp.async.cg.shared.global [%0], [%1], 16;\n" :: "r"(s), "l"(g));
}
#define CP_COMMIT() asm volatile("cp.async.commit_group;\n" ::)
#define CP_WAIT1()  asm volatile("cp.async.wait_group 1;\n" ::)

__device__ __forceinline__ void mma_tf32(float* d, const uint32_t* a, const uint32_t* b)
{
    asm volatile(
        "mma.sync.aligned.m16n8k8.row.col.f32.tf32.tf32.f32 "
        "{%0,%1,%2,%3},{%4,%5,%6,%7},{%8,%9},{%0,%1,%2,%3};"
        : "+f"(d[0]), "+f"(d[1]), "+f"(d[2]), "+f"(d[3])
        : "r"(a[0]), "r"(a[1]), "r"(a[2]), "r"(a[3]), "r"(b[0]), "r"(b[1]));
}

// ---------------- tf32 tensor-core GEMM (static smem, BK=16, 2-stage) ----------
// 128 threads, 4 warps in 2x2, warp tile 64x64; all fragments batched per k-tile
#define ASTRIDE 24          // 16 + 8 pad (floats)
#define BSTRIDE 136         // 128 + 8 pad
#define ATILE (128*ASTRIDE)
#define BTILE (16*BSTRIDE)
#define STAGEF (ATILE + BTILE) // 21KB per stage; 2 stages = 42KB static

// C = alpha*(A@B) [+bias] [relu] [+resid]; tri => K truncated to m0+128
template<bool RELU, bool RESID, bool OUTTF>
__global__ void __launch_bounds__(128)
mma_gemm(int M, int N, int K,
         const float* __restrict__ A, int lda, long long sAh, long long sAb,
         const float* __restrict__ Bm, int ldb, long long sBh, long long sBb,
         float* __restrict__ C, int ldc, long long sCh, long long sCb,
         const float* __restrict__ bias, const float* __restrict__ resid,
         float alpha, int zB, int tri)
{
    __shared__ float sm[2*STAGEF];
    const int tid = threadIdx.x;
    const int z = blockIdx.z;
    const int zh = z / zB, zb = z % zB;
    A    += zh*sAh + zb*sAb;
    Bm   += zh*sBh + zb*sBb;
    long long coff = zh*sCh + zb*sCb;
    C    += coff;
    const float* res = RESID ? (resid + coff) : nullptr;

    const int m0 = blockIdx.x * 128;
    const int n0 = blockIdx.y * 128;

    const int warp = tid >> 5, lane = tid & 31;
    const int wm = warp >> 1, wn = warp & 1;     // 2x2 warps, warp tile 64x64
    const int grp = lane >> 2, tig = lane & 3;

    float acc[4][8][4];
#pragma unroll
    for (int i = 0; i < 4; i++)
#pragma unroll
        for (int j = 0; j < 8; j++)
#pragma unroll
            for (int k = 0; k < 4; k++) acc[i][j][k] = 0.0f;

    int Ke = tri ? (m0 + 128 < K ? m0 + 128 : K) : K;
    const int nk = Ke >> 4;   // K/16

    auto load_tile = [&](int st, int k0) {
        float* As = sm + st*STAGEF;
        float* Bs = sm + st*STAGEF + ATILE;
#pragma unroll
        for (int i = 0; i < 4; i++) {            // 512 float4 for A (128x16)
            int idx = tid + i*128;
            int r  = idx >> 2, c4 = idx & 3;
            cp16(&As[r*ASTRIDE + c4*4], &A[(long long)(m0 + r)*lda + k0 + c4*4]);
        }
#pragma unroll
        for (int i = 0; i < 4; i++) {            // 512 float4 for B (16x128)
            int idx = tid + i*128;
            int r  = idx >> 5, c4 = idx & 31;
            cp16(&Bs[r*BSTRIDE + c4*4], &Bm[(long long)(k0 + r)*ldb + n0 + c4*4]);
        }
    };

    load_tile(0, 0);
    CP_COMMIT();

    for (int kt = 0; kt < nk; kt++) {
        if (kt + 1 < nk) load_tile((kt + 1) & 1, (kt + 1) << 4);
        CP_COMMIT();
        CP_WAIT1();
        __syncthreads();

        const float* As = sm + (kt & 1)*STAGEF;
        const float* Bs = sm + (kt & 1)*STAGEF + ATILE;

        // batch-load ALL fragments for both kk-halves, then stream 64 MMAs
        uint32_t af[2][4][4], bf[2][8][2];
#pragma unroll
        for (int kh = 0; kh < 2; kh++) {
            int kk = kh << 3;
#pragma unroll
            for (int mt = 0; mt < 4; mt++) {
                int row = wm*64 + mt*16;
                af[kh][mt][0] = __float_as_uint(As[(row + grp    )*ASTRIDE + kk + tig    ]);
                af[kh][mt][1] = __float_as_uint(As[(row + grp + 8)*ASTRIDE + kk + tig    ]);
                af[kh][mt][2] = __float_as_uint(As[(row + grp    )*ASTRIDE + kk + tig + 4]);
                af[kh][mt][3] = __float_as_uint(As[(row + grp + 8)*ASTRIDE + kk + tig + 4]);
            }
#pragma unroll
            for (int nt = 0; nt < 8; nt++) {
                int col = wn*64 + nt*8 + grp;
                bf[kh][nt][0] = __float_as_uint(Bs[(kk + tig    )*BSTRIDE + col]);
                bf[kh][nt][1] = __float_as_uint(Bs[(kk + tig + 4)*BSTRIDE + col]);
            }
        }
#pragma unroll
        for (int kh = 0; kh < 2; kh++)
#pragma unroll
            for (int mt = 0; mt < 4; mt++)
#pragma unroll
                for (int nt = 0; nt < 8; nt++)
                    mma_tf32(acc[mt][nt], af[kh][mt], bf[kh][nt]);
        __syncthreads();
    }

#pragma unroll
    for (int mt = 0; mt < 4; mt++) {
        int r0 = m0 + wm*64 + mt*16 + grp;
#pragma unroll
        for (int nt = 0; nt < 8; nt++) {
            int c = n0 + wn*64 + nt*8 + tig*2;
            float v00 = acc[mt][nt][0]*alpha, v01 = acc[mt][nt][1]*alpha;
            float v10 = acc[mt][nt][2]*alpha, v11 = acc[mt][nt][3]*alpha;
            if (bias) {
                float2 bv2 = *(const float2*)&bias[c];
                v00 += bv2.x; v01 += bv2.y; v10 += bv2.x; v11 += bv2.y;
            }
            if (RELU) {
                v00 = fmaxf(v00, 0.0f); v01 = fmaxf(v01, 0.0f);
                v10 = fmaxf(v10, 0.0f); v11 = fmaxf(v11, 0.0f);
            }
            long long i0 = (long long)r0*ldc + c;
            long long i1 = (long long)(r0 + 8)*ldc + c;
            if (RESID) {
                float2 e0 = *(const float2*)&res[i0];
                float2 e1 = *(const float2*)&res[i1];
                v00 += e0.x; v01 += e0.y; v10 += e1.x; v11 += e1.y;
            }
            if (OUTTF) {
                v00 = f2tff(v00); v01 = f2tff(v01);
                v10 = f2tff(v10); v11 = f2tff(v11);
            }
            *(float2*)&C[i0] = make_float2(v00, v01);
            *(float2*)&C[i1] = make_float2(v10, v11);
        }
    }
}

// ---------------- scores on tensor cores: Q @ K^T / 8, lower tiles only --------
// Q rows: g_QK[s][h*64..], K rows: g_QK[t][1024 + h*64..], row stride QKN
#define QSTR 24             // A tile stride (16+8)
#define KSTR 20             // B tile stride (16+4)
#define SQTILE (128*QSTR)
#define SKTILE (128*KSTR)
#define SSTAGE (SQTILE + SKTILE)

__global__ void __launch_bounds__(256)
scores_mma_kernel(const float* __restrict__ QK, float* __restrict__ ATT)
{
    const int s0 = blockIdx.x * 128;
    const int t0 = blockIdx.y * 128;
    if (t0 > s0) return;               // strictly-upper tile: never read downstream

    __shared__ float sm[2*SSTAGE];
    const int z = blockIdx.z;          // h*B + b
    const int b = z % B_;
    const int h = z / B_;
    float* att = ATT + (long long)z * S_ * S_;
    const int tid = threadIdx.x;

    const float* Qh = QK + (long long)(b*S_)*QKN + h*KD_;
    const float* Kh = QK + (long long)(b*S_)*QKN + D_ + h*KD_;
    const unsigned char* padb = g_pad + b*S_;

    const int warp = tid >> 5, lane = tid & 31;
    const int wm = warp >> 1, wn = warp & 1;
    const int grp = lane >> 2, tig = lane & 3;

    float acc[2][8][4];
#pragma unroll
    for (int i = 0; i < 2; i++)
#pragma unroll
        for (int j = 0; j < 8; j++)
#pragma unroll
            for (int k = 0; k < 4; k++) acc[i][j][k] = 0.0f;

    auto load_tile = [&](int st, int k0) {
        float* Qs = sm + st*SSTAGE;
        float* Ks = sm + st*SSTAGE + SQTILE;
#pragma unroll
        for (int i = 0; i < 2; i++) {
            int idx = tid + i*256;
            int r  = idx >> 2, c4 = idx & 3;
            cp16(&Qs[r*QSTR + c4*4], &Qh[(long long)(s0 + r)*QKN + k0 + c4*4]);
        }
#pragma unroll
        for (int i = 0; i < 2; i++) {
            int idx = tid + i*256;
            int r  = idx >> 2, c4 = idx & 3;
            cp16(&Ks[r*KSTR + c4*4], &Kh[(long long)(t0 + r)*QKN + k0 + c4*4]);
        }
    };

    load_tile(0, 0);
    CP_COMMIT();

    const int nk = KD_ / 16;   // 4
#pragma unroll
    for (int kt = 0; kt < nk; kt++) {
        if (kt + 1 < nk) load_tile((kt + 1) & 1, (kt + 1) << 4);
        CP_COMMIT();
        CP_WAIT1();
        __syncthreads();

        const float* Qs = sm + (kt & 1)*SSTAGE;
        const float* Ks = sm + (kt & 1)*SSTAGE + SQTILE;
#pragma unroll
        for (int kk = 0; kk < 16; kk += 8) {
            uint32_t af[2][4], bf[8][2];
#pragma unroll
            for (int mt = 0; mt < 2; mt++) {
                int row = wm*32 + mt*16;
                af[mt][0] = __float_as_uint(Qs[(row + grp    )*QSTR + kk + tig    ]);
                af[mt][1] = __float_as_uint(Qs[(row + grp + 8)*QSTR + kk + tig    ]);
                af[mt][2] = __float_as_uint(Qs[(row + grp    )*QSTR + kk + tig + 4]);
                af[mt][3] = __float_as_uint(Qs[(row + grp + 8)*QSTR + kk + tig + 4]);
            }
#pragma unroll
            for (int nt = 0; nt < 8; nt++) {
                int col = wn*64 + nt*8 + grp;
                bf[nt][0] = __float_as_uint(Ks[col*KSTR + kk + tig    ]);
                bf[nt][1] = __float_as_uint(Ks[col*KSTR + kk + tig + 4]);
            }
#pragma unroll
            for (int mt = 0; mt < 2; mt++)
#pragma unroll
                for (int nt = 0; nt < 8; nt++)
                    mma_tf32(acc[mt][nt], af[mt], bf[nt]);
        }
        __syncthreads();
    }

    // epilogue: mask + scale, write fp32 scores
#pragma unroll
    for (int mt = 0; mt < 2; mt++) {
        int r0 = wm*32 + mt*16 + grp;
#pragma unroll
        for (int nt = 0; nt < 8; nt++) {
            int c = wn*64 + nt*8 + tig*2;
#pragma unroll
            for (int half = 0; half < 2; half++) {
                int s = s0 + r0 + half*8;
                unsigned char pads = padb[s];
                long long base = (long long)s * S_;
#pragma unroll
                for (int q = 0; q < 2; q++) {
                    int t = t0 + c + q;
                    float v = acc[mt][nt][half*2 + q] * 0.125f;
                    bool masked = (t > s) || pads || padb[t];
                    att[base + t] = masked ? -1e30f : v;
                }
            }
        }
    }
}

// ---------------- causal softmax: probs written as tf32 bits -------------------
__global__ void __launch_bounds__(256)
softmax_kernel(float* __restrict__ ATT)
{
    const long long row = blockIdx.x;
    const int s = (int)(row % S_);
    float* p = ATT + row * S_;
    const int tid = threadIdx.x;
    const int L  = s + 1;
    const int Lw = ((s >> 7) + 1) << 7;   // round_up(s+1, 128)

    float v[8];
    float m = -1e30f;
#pragma unroll
    for (int j = 0; j < 8; j++) {
        int i = tid + j*256;
        v[j] = (i < L) ? p[i] : -1e30f;
        m = fmaxf(m, v[j]);
    }
    __shared__ float red[256];
    red[tid] = m; __syncthreads();
    for (int st = 128; st > 0; st >>= 1) {
        if (tid < st) red[tid] = fmaxf(red[tid], red[tid + st]);
        __syncthreads();
    }
    float rowmax = red[0];
    __syncthreads();
    if (rowmax < -1e29f) {                // fully masked row: zero (fixup later)
#pragma unroll
        for (int j = 0; j < 8; j++) {
            int i = tid + j*256;
            if (i < Lw) p[i] = 0.0f;
        }
        return;
    }
    float sum = 0.0f;
#pragma unroll
    for (int j = 0; j < 8; j++) {
        int i = tid + j*256;
        if (i < L) { v[j] = __expf(v[j] - rowmax); sum += v[j]; }
        else v[j] = 0.0f;
    }
    red[tid] = sum; __syncthreads();
    for (int st = 128; st > 0; st >>= 1) {
        if (tid < st) red[tid] += red[tid + st];
        __syncthreads();
    }
    float inv = 1.0f / red[0];
#pragma unroll
    for (int j = 0; j < 8; j++) {
        int i = tid + j*256;
        if (i < L) p[i] = f2tff(v[j] * inv);
        else if (i < Lw) p[i] = 0.0f;
    }
}

// ---------------- layernorm (optional residual add; optional tf32 copy) --------
__global__ void __launch_bounds__(256)
ln_kernel(float* __restrict__ out, float* __restrict__ out32,
          const float* __restrict__ a, const float* __restrict__ r,
          const float* __restrict__ w, const float* __restrict__ bb)
{
    long long base = (long long)blockIdx.x * D_;
    const int tid = threadIdx.x;
    float x[4];
    float sum = 0.0f, sq = 0.0f;
#pragma unroll
    for (int i = 0; i < 4; i++) {
        int c = tid + i*256;
        float v = a[base + c];
        if (r) v += r[base + c];
        x[i] = v; sum += v; sq += v*v;
    }
    __shared__ float r1[256], r2[256];
    r1[tid] = sum; r2[tid] = sq; __syncthreads();
    for (int s = 128; s > 0; s >>= 1) {
        if (tid < s) { r1[tid] += r1[tid + s]; r2[tid] += r2[tid + s]; }
        __syncthreads();
    }
    float mu  = r1[0] * (1.0f / D_);
    float var = r2[0] * (1.0f / D_) - mu*mu;
    float rstd = rsqrtf(var + 1e-5f);
#pragma unroll
    for (int i = 0; i < 4; i++) {
        int c = tid + i*256;
        float o = (x[i] - mu) * rstd * w[c] + bb[c];
        out[base + c] = o;
        if (out32) out32[base + c] = f2tff(o);
    }
}

// ---------------- launch --------------------------------------------------------
extern "C" void kernel_launch(void* const* d_in, const int* in_sizes, int n_in,
                              void* d_out, int out_size)
{
    const float* input = (const float*)d_in[0];
    const void*  mraw  = d_in[1];
    const float* Wq    = (const float*)d_in[2];
    const float* bq    = (const float*)d_in[3];
    const float* Wk    = (const float*)d_in[4];
    const float* bk    = (const float*)d_in[5];
    const float* Wv    = (const float*)d_in[6];
    const float* bv    = (const float*)d_in[7];
    const float* ln1w  = (const float*)d_in[8];
    const float* ln1b  = (const float*)d_in[9];
    const float* ln2w  = (const float*)d_in[10];
    const float* ln2b  = (const float*)d_in[11];
    const float* ff1w  = (const float*)d_in[12];
    const float* ff1b  = (const float*)d_in[13];
    const float* ff2w  = (const float*)d_in[14];
    const float* ff2b  = (const float*)d_in[15];
    float* out = (float*)d_out;

    float *pQK, *pATT, *pCTX, *pAV, *pX, *pX32, *pFF, *pWqk2, *pBqk, *pBvm;
    float *pIN32, *pWv32, *pF1w, *pF2w;
    cudaGetSymbolAddress((void**)&pQK,   g_QK);
    cudaGetSymbolAddress((void**)&pATT,  g_ATT);
    cudaGetSymbolAddress((void**)&pCTX,  g_CTX);
    cudaGetSymbolAddress((void**)&pAV,   g_AV);
    cudaGetSymbolAddress((void**)&pX,    g_X);
    cudaGetSymbolAddress((void**)&pX32,  g_X32);
    cudaGetSymbolAddress((void**)&pFF,   g_FF);
    cudaGetSymbolAddress((void**)&pWqk2, g_Wqk2);
    cudaGetSymbolAddress((void**)&pBqk,  g_bqk);
    cudaGetSymbolAddress((void**)&pBvm,  g_bvm);
    cudaGetSymbolAddress((void**)&pIN32, g_IN32);
    cudaGetSymbolAddress((void**)&pWv32, g_Wv32);
    cudaGetSymbolAddress((void**)&pF1w,  g_ff1w32);
    cudaGetSymbolAddress((void**)&pF2w,  g_ff2w32);

    // launches 1..3 (prep)
    prep_mask_kernel<<<1, 256>>>(mraw);
    repack_wqk_kernel<<<4096, 256>>>(Wq, Wk);
    cvt_all_kernel<<<(N4_IN+N4_WV+N4_F1+N4_F2)/256, 256>>>(input, Wv, ff1w, ff2w, bq, bk);

    // launch 4: fused QK projection [8192,2048,1024] -- ncu capture slot
    mma_gemm<false,false,true><<<dim3(BS_/128, QKN/128, 1), 128>>>(
        BS_, QKN, D_,
        pIN32, D_, 0LL, 0LL,
        pWqk2, QKN, 0LL, 0LL,
        pQK, QKN, 0LL, 0LL,
        pBqk, nullptr, 1.0f, 1, 0);

    // launches 5,6: scores (lower tiles) + causal softmax (tf32 probs)
    scores_mma_kernel<<<dim3(S_/128, S_/128, H_*B_), 256>>>(pQK, pATT);
    softmax_kernel<<<H_*B_*S_, 256>>>(pATT);

    // launches 7,8: colsum prep (needed before ctx_fixup / Wv gemm)
    misc_kernel<<<B_*D_/256, 256>>>(bv);
    colsum_kernel<<<B_*32, 256>>>(input);

    // CTX = attn_h,b @ input_b  (tri-truncated K), output tf32; padded-row fixup
    mma_gemm<false,false,true><<<dim3(S_/128, D_/128, H_*B_), 128>>>(
        S_, D_, S_,
        pATT, S_, (long long)B_*S_*S_, (long long)S_*S_,
        pIN32, D_, 0LL, (long long)S_*D_,
        pCTX, HD_, (long long)D_, (long long)S_*HD_,
        nullptr, nullptr, 1.0f, B_, 1 /*tri*/);
    ctx_fixup_kernel<<<BS_, 256>>>();

    // AV = CTX[8192,16384] @ Wv_flat[16384,1024] / H + mean bias (fp32 out)
    mma_gemm<false,false,false><<<dim3(BS_/128, D_/128, 1), 128>>>(
        BS_, D_, HD_,
        pCTX, HD_, 0LL, 0LL,
        pWv32, D_, 0LL, 0LL,
        pAV, D_, 0LL, 0LL,
        pBvm, nullptr, 1.0f/H_, 1, 0);

    // x = LN1(input + AV); fp32 + tf32 copies
    ln_kernel<<<BS_, 256>>>(pX, pX32, input, pAV, ln1w, ln1b);

    // FFN
    mma_gemm<true,false,true><<<dim3(BS_/128, FF_/128, 1), 128>>>(
        BS_, FF_, D_,
        pX32, D_, 0LL, 0LL,
        pF1w, FF_, 0LL, 0LL,
        pFF, FF_, 0LL, 0LL,
        ff1b, nullptr, 1.0f, 1, 0);
    mma_gemm<false,true,false><<<dim3(BS_/128, D_/128, 1), 128>>>(
        BS_, D_, FF_,
        pFF, FF_, 0LL, 0LL,
        pF2w, D_, 0LL, 0LL,
        pAV, D_, 0LL, 0LL,
        ff2b, pX, 1.0f, 1, 0);

    // out = LN2(x + ff)
    ln_kernel<<<BS_, 256>>>(out, nullptr, pAV, nullptr, ln2w, ln2b);
}